// round 13
// baseline (speedup 1.0000x reference)
#include <cuda_runtime.h>
#include <cuda_bf16.h>
#include <math.h>
#include <stdint.h>

// Problem constants
#define T_SEQ  4096
#define D_MODEL 1024
#define NH     16
#define NKV    4
#define HD     64
#define D_FF   4096

// ---------------- scratch (device globals; no allocation allowed) ----------
__device__ float g_q[T_SEQ * D_MODEL];
__device__ float g_k[T_SEQ * NKV * HD];         // [token][256] (pre-rope)
__device__ float g_v[NKV * HD * T_SEQ];         // TRANSPOSED [256][4096]
__device__ float g_attn[T_SEQ * D_MODEL];       // tf32-rounded
__device__ float g_h1[(size_t)T_SEQ * D_FF];    // tf32-rounded
__device__ float g_cos[T_SEQ * 32];
__device__ float g_sin[T_SEQ * 32];
__device__ float g_xt[T_SEQ * D_MODEL];
__device__ float g_wqt[D_MODEL * D_MODEL];
__device__ float g_wkt[D_MODEL * NKV * HD];
__device__ float g_wvt[D_MODEL * NKV * HD];
__device__ float g_w1t[D_MODEL * D_FF];
__device__ float g_w2t[D_FF * D_MODEL];
__device__ uint32_t g_khp[T_SEQ * 128];         // [token][kvh*32 + d2] bf16x2 hi
__device__ uint32_t g_klp[T_SEQ * 128];
__device__ uint32_t g_vhp[NKV * HD * (T_SEQ / 2)];  // [dim][token-pair]
__device__ uint32_t g_vlp[NKV * HD * (T_SEQ / 2)];

// ---------------- helpers ---------------------------------------------------
__device__ __forceinline__ uint32_t f2tf32(float x) {
    uint32_t r;
    asm("cvt.rna.tf32.f32 %0, %1;" : "=r"(r) : "f"(x));
    return r;
}
__device__ __forceinline__ float roundtf(float x) {
    return __uint_as_float(f2tf32(x));
}

__device__ __forceinline__ void mma_tf32(float* d, const uint32_t* a,
                                         const uint32_t* b, const float* c) {
    asm volatile(
        "mma.sync.aligned.m16n8k8.row.col.f32.tf32.tf32.f32 "
        "{%0,%1,%2,%3}, {%4,%5,%6,%7}, {%8,%9}, {%10,%11,%12,%13};"
        : "=f"(d[0]), "=f"(d[1]), "=f"(d[2]), "=f"(d[3])
        : "r"(a[0]), "r"(a[1]), "r"(a[2]), "r"(a[3]),
          "r"(b[0]), "r"(b[1]),
          "f"(c[0]), "f"(c[1]), "f"(c[2]), "f"(c[3]));
}

__device__ __forceinline__ void mma_bf16(float* d, const uint32_t* a,
                                         const uint32_t* b, const float* c) {
    asm volatile(
        "mma.sync.aligned.m16n8k16.row.col.f32.bf16.bf16.f32 "
        "{%0,%1,%2,%3}, {%4,%5,%6,%7}, {%8,%9}, {%10,%11,%12,%13};"
        : "=f"(d[0]), "=f"(d[1]), "=f"(d[2]), "=f"(d[3])
        : "r"(a[0]), "r"(a[1]), "r"(a[2]), "r"(a[3]),
          "r"(b[0]), "r"(b[1]),
          "f"(c[0]), "f"(c[1]), "f"(c[2]), "f"(c[3]));
}

__device__ __forceinline__ void ldsm_x4(uint32_t& r0, uint32_t& r1,
                                        uint32_t& r2, uint32_t& r3,
                                        uint32_t saddr) {
    asm volatile(
        "ldmatrix.sync.aligned.m8n8.x4.shared.b16 {%0,%1,%2,%3}, [%4];"
        : "=r"(r0), "=r"(r1), "=r"(r2), "=r"(r3) : "r"(saddr));
}

__device__ __forceinline__ uint32_t packbf(float x, float y) {
    __nv_bfloat162 t = __floats2bfloat162_rn(x, y);
    return *(uint32_t*)&t;
}
__device__ __forceinline__ void splitbf(float x, float y,
                                        uint32_t& hi, uint32_t& lo) {
    __nv_bfloat16 hx = __float2bfloat16_rn(x);
    __nv_bfloat16 hy = __float2bfloat16_rn(y);
    hi = packbf(__bfloat162float(hx), __bfloat162float(hy));
    lo = packbf(x - __bfloat162float(hx), y - __bfloat162float(hy));
}

__device__ __forceinline__ void cp16(float* smem_dst, const float* g) {
    uint32_t a = (uint32_t)__cvta_generic_to_shared(smem_dst);
    asm volatile("cp.async.ca.shared.global [%0], [%1], 16;" :: "r"(a), "l"(g));
}
__device__ __forceinline__ void cp16u(uint32_t* smem_dst, const uint32_t* g) {
    uint32_t a = (uint32_t)__cvta_generic_to_shared(smem_dst);
    asm volatile("cp.async.ca.shared.global [%0], [%1], 16;" :: "r"(a), "l"(g));
}

// ---------------- merged pre-round pass -------------------------------------
// Segments (float4-blocks of 256):
//   X 4096 | Wq 1024 | Wk 256 | Wv 256 | W1 4096 | W2 4096 => 13824 blocks
__global__ void round_all_kernel(
    const float* __restrict__ X,  const float* __restrict__ Wq,
    const float* __restrict__ Wk, const float* __restrict__ Wv,
    const float* __restrict__ W1, const float* __restrict__ W2)
{
    int b = blockIdx.x;
    const float* src;
    float* dst;
    int base;
    if      (b < 4096) { src = X;  dst = g_xt;  base = 0;    }
    else if (b < 5120) { src = Wq; dst = g_wqt; base = 4096; }
    else if (b < 5376) { src = Wk; dst = g_wkt; base = 5120; }
    else if (b < 5632) { src = Wv; dst = g_wvt; base = 5376; }
    else if (b < 9728) { src = W1; dst = g_w1t; base = 5632; }
    else               { src = W2; dst = g_w2t; base = 9728; }
    int i = (b - base) * 256 + threadIdx.x;
    float4 v = ((const float4*)src)[i];
    v.x = roundtf(v.x); v.y = roundtf(v.y);
    v.z = roundtf(v.z); v.w = roundtf(v.w);
    ((float4*)dst)[i] = v;
}

// ---------------- RoPE ------------------------------------------------------
__global__ void rope_table_kernel() {
    int t = blockIdx.x, i = threadIdx.x;
    float inv = 1.0f / powf(10000.0f, (float)(2 * i) / 64.0f);
    float ang = (float)t * inv;
    g_cos[t * 32 + i] = cosf(ang);
    g_sin[t * 32 + i] = sinf(ang);
}

__global__ void rope_apply_kernel(float* __restrict__ x, int nh) {
    int t = blockIdx.x;
    int h = threadIdx.x >> 5;
    int i = threadIdx.x & 31;
    float c = g_cos[t * 32 + i];
    float s = g_sin[t * 32 + i];
    float* p = x + (size_t)t * nh * HD + h * HD;
    float x1 = p[i], x2 = p[i + 32];
    p[i]      = x1 * c - x2 * s;
    p[i + 32] = x2 * c + x1 * s;
}

// ---------------- fused KV prep ---------------------------------------------
__global__ void prep_kv_kernel() {
    int b = blockIdx.x;
    if (b < 2048) {
        __shared__ float buf[2][NKV][64];
        int sub = threadIdx.x >> 7;
        int wt  = threadIdx.x & 127;
        int t = b * 2 + sub;
        int h = wt >> 5;
        int i = wt & 31;
        float c = g_cos[t * 32 + i];
        float s = g_sin[t * 32 + i];
        const float* p = g_k + (size_t)t * (NKV * HD) + h * HD;
        float x1 = p[i], x2 = p[i + 32];
        buf[sub][h][i]      = x1 * c - x2 * s;
        buf[sub][h][i + 32] = x2 * c + x1 * s;
        __syncthreads();
        float a = buf[sub][h][2 * i], bb = buf[sub][h][2 * i + 1];
        uint32_t hi, lo;
        splitbf(a, bb, hi, lo);
        g_khp[t * 128 + h * 32 + i] = hi;
        g_klp[t * 128 + h * 32 + i] = lo;
    } else {
        int idx = (b - 2048) * 256 + threadIdx.x;
        float2 v = *(const float2*)&g_v[(size_t)idx * 2];
        uint32_t hi, lo;
        splitbf(v.x, v.y, hi, lo);
        g_vhp[idx] = hi;
        g_vlp[idx] = lo;
    }
}

// ---------------- cp.async tf32 GEMM (R10 proven: BK=16, 4-stage, ldsm A) ---
#define AS_ST 20
#define BS_ST 136
#define AS_STAGE (128 * AS_ST)
#define BS_STAGE (16 * BS_ST)
#define GEMM_SMEM ((4 * (AS_STAGE + BS_STAGE)) * 4)

template <int SILU, int ROUND, int TRANSC>
__device__ __forceinline__ void gemm_body(
    const float* __restrict__ A, const float* __restrict__ B,
    float* __restrict__ C, int N, int K, int rowBase, int colBase)
{
    extern __shared__ float smp[];
    float* As = smp;
    float* Bs = smp + 4 * AS_STAGE;

    int tid  = threadIdx.x;
    int lane = tid & 31;
    int warp = tid >> 5;
    int wm = (warp & 1) * 64;
    int wn = (warp >> 1) * 32;

    int ar  = tid >> 2;
    int ac  = (tid & 3) << 2;
    int bkr = tid >> 5;
    int bc  = (tid & 31) << 2;

    const float* Ag0 = A + (size_t)(rowBase + ar) * K + ac;
    const float* Ag1 = A + (size_t)(rowBase + 64 + ar) * K + ac;
    const float* Bg  = B + colBase + bc;

    uint32_t smem_b = (uint32_t)__cvta_generic_to_shared(smp);
    uint32_t loA = ((wm + (lane & 7) + ((lane >> 3) & 1) * 8) * AS_ST
                    + (lane >> 4) * 4) * 4;

    int nk = K >> 4;

#pragma unroll
    for (int s = 0; s < 3; s++) {
        if (s < nk) {
            float* as = As + s * AS_STAGE;
            float* bs = Bs + s * BS_STAGE;
            int k0 = s << 4;
            cp16(as + ar * AS_ST + ac,        Ag0 + k0);
            cp16(as + (ar + 64) * AS_ST + ac, Ag1 + k0);
            cp16(bs + bkr * BS_ST + bc,       Bg + (size_t)(k0 + bkr) * N);
            cp16(bs + (bkr + 8) * BS_ST + bc, Bg + (size_t)(k0 + 8 + bkr) * N);
        }
        asm volatile("cp.async.commit_group;");
    }

    float acc[4][4][4];
#pragma unroll
    for (int i = 0; i < 4; i++)
#pragma unroll
        for (int j = 0; j < 4; j++)
#pragma unroll
            for (int q = 0; q < 4; q++) acc[i][j][q] = 0.0f;

    for (int kt = 0; kt < nk; kt++) {
        asm volatile("cp.async.wait_group 2;");
        __syncthreads();

        int nx = kt + 3;
        if (nx < nk) {
            int bufn = nx & 3;
            float* as = As + bufn * AS_STAGE;
            float* bs = Bs + bufn * BS_STAGE;
            int k0 = nx << 4;
            cp16(as + ar * AS_ST + ac,        Ag0 + k0);
            cp16(as + (ar + 64) * AS_ST + ac, Ag1 + k0);
            cp16(bs + bkr * BS_ST + bc,       Bg + (size_t)(k0 + bkr) * N);
            cp16(bs + (bkr + 8) * BS_ST + bc, Bg + (size_t)(k0 + 8 + bkr) * N);
        }
        asm volatile("cp.async.commit_group;");

        uint32_t asb = smem_b + ((kt & 3) * AS_STAGE) * 4 + loA;
        const float* bs = Bs + (kt & 3) * BS_STAGE;
#pragma unroll
        for (int ks = 0; ks < 16; ks += 8) {
            uint32_t af[4][4], bf[4][2];
#pragma unroll
            for (int i = 0; i < 4; i++) {
                ldsm_x4(af[i][0], af[i][1], af[i][2], af[i][3],
                        asb + (i * 16 * AS_ST + ks) * 4);
            }
#pragma unroll
            for (int j = 0; j < 4; j++) {
                int kk = ks + (lane & 3);
                int n  = wn + j * 8 + (lane >> 2);
                bf[j][0] = __float_as_uint(bs[kk * BS_ST + n]);
                bf[j][1] = __float_as_uint(bs[(kk + 4) * BS_ST + n]);
            }
#pragma unroll
            for (int i = 0; i < 4; i++)
#pragma unroll
                for (int j = 0; j < 4; j++)
                    mma_tf32(acc[i][j], af[i], bf[j], acc[i][j]);
        }
    }

#pragma unroll
    for (int i = 0; i < 4; i++) {
        int r0 = rowBase + wm + i * 16 + (lane >> 2);
#pragma unroll
        for (int j = 0; j < 4; j++) {
            int c0 = colBase + wn + j * 8 + (lane & 3) * 2;
            float2 v0, v1;
            v0.x = acc[i][j][0]; v0.y = acc[i][j][1];
            v1.x = acc[i][j][2]; v1.y = acc[i][j][3];
            if (SILU) {
                v0.x = v0.x / (1.0f + expf(-v0.x));
                v0.y = v0.y / (1.0f + expf(-v0.y));
                v1.x = v1.x / (1.0f + expf(-v1.x));
                v1.y = v1.y / (1.0f + expf(-v1.y));
            }
            if (ROUND) {
                v0.x = roundtf(v0.x); v0.y = roundtf(v0.y);
                v1.x = roundtf(v1.x); v1.y = roundtf(v1.y);
            }
            if (TRANSC) {
                C[(size_t)c0 * T_SEQ + r0]           = v0.x;
                C[(size_t)(c0 + 1) * T_SEQ + r0]     = v0.y;
                C[(size_t)c0 * T_SEQ + r0 + 8]       = v1.x;
                C[(size_t)(c0 + 1) * T_SEQ + r0 + 8] = v1.y;
            } else {
                *(float2*)&C[(size_t)r0 * N + c0]       = v0;
                *(float2*)&C[(size_t)(r0 + 8) * N + c0] = v1;
            }
        }
    }
}

template <int SILU, int ROUND>
__global__ void __launch_bounds__(256, 2) tgemm2_kernel(
    const float* __restrict__ A, const float* __restrict__ B,
    float* __restrict__ C, int N, int K)
{
    gemm_body<SILU, ROUND, 0>(A, B, C, N, K, blockIdx.y * 128, blockIdx.x * 128);
}

__global__ void __launch_bounds__(256, 2) qkv_kernel(
    const float* __restrict__ Xt,
    const float* __restrict__ Wqt, const float* __restrict__ Wkt,
    const float* __restrict__ Wvt,
    float* __restrict__ q, float* __restrict__ k, float* __restrict__ v)
{
    int bx = blockIdx.x;
    if (bx < 8) {
        gemm_body<0, 0, 0>(Xt, Wqt, q, D_MODEL, D_MODEL,
                           blockIdx.y * 128, bx * 128);
    } else if (bx < 10) {
        gemm_body<0, 0, 0>(Xt, Wkt, k, NKV * HD, D_MODEL,
                           blockIdx.y * 128, (bx - 8) * 128);
    } else {
        gemm_body<0, 0, 1>(Xt, Wvt, v, NKV * HD, D_MODEL,
                           blockIdx.y * 128, (bx - 10) * 128);
    }
}

// ---------------- bf16 MMA flash attention (BM=64, BN=128, 3 CTAs/SM) ------
// Single-stage smem: K 128 rows x 68 u32 (32 hi | 32 lo | pad),
//                    V  64 rows x 132 u32 (64 hi | 64 lo | pad) = 68608 B.
// 128 threads (4 warps x 16 rows). Cross-CTA overlap replaces double buffer.
#define KR_K 68
#define KR_V 132
#define KARR (128 * KR_K)           // 8704 u32
#define VARR (64 * KR_V)            // 8448 u32
#define STAGE_U (KARR + VARR)       // 17152 u32
#define ATT_SMEM (STAGE_U * 4)      // 68608 bytes

__global__ void __launch_bounds__(128, 3) attn_bf16_kernel(
    const float* __restrict__ qp,
    const uint32_t* __restrict__ khp, const uint32_t* __restrict__ klp,
    const uint32_t* __restrict__ vhp, const uint32_t* __restrict__ vlp,
    float* __restrict__ op)
{
    extern __shared__ uint32_t smu[];
    float* Qs = (float*)smu;                  // Q staging, pre-loop only

    int qb   = gridDim.x - 1 - blockIdx.x;    // 0..63, heavy blocks first
    int h    = blockIdx.y;
    int kvh  = h >> 2;
    int tid  = threadIdx.x;
    int lane = tid & 31;
    int warp = tid >> 5;                       // 0..3
    int gid  = lane >> 2;
    int tig  = lane & 3;
    int tg2  = tig * 2;
    int fr   = warp * 16 + gid;                // 0..63

    // ---- stage Q tile (64 rows x 64 floats) ----
#pragma unroll
    for (int i = 0; i < 8; i++) {
        int e = tid + 128 * i;                 // 1024 float4 groups
        int r = e >> 4, c4 = (e & 15) << 2;
        *(float4*)&Qs[r * 64 + c4] =
            *(const float4*)&qp[(size_t)(qb * 64 + r) * D_MODEL + h * HD + c4];
    }
    __syncthreads();

    uint32_t qhi[4][4], qlo[4][4];
#pragma unroll
    for (int kt = 0; kt < 4; kt++) {
        float2 x0 = *(float2*)&Qs[fr * 64 + kt * 16 + tg2];
        float2 x1 = *(float2*)&Qs[(fr + 8) * 64 + kt * 16 + tg2];
        float2 x2 = *(float2*)&Qs[fr * 64 + kt * 16 + tg2 + 8];
        float2 x3 = *(float2*)&Qs[(fr + 8) * 64 + kt * 16 + tg2 + 8];
        splitbf(x0.x * 0.125f, x0.y * 0.125f, qhi[kt][0], qlo[kt][0]);
        splitbf(x1.x * 0.125f, x1.y * 0.125f, qhi[kt][1], qlo[kt][1]);
        splitbf(x2.x * 0.125f, x2.y * 0.125f, qhi[kt][2], qlo[kt][2]);
        splitbf(x3.x * 0.125f, x3.y * 0.125f, qhi[kt][3], qlo[kt][3]);
    }
    __syncthreads();   // Q reads done before cp.async overwrites stage

    uint32_t smem_b = (uint32_t)__cvta_generic_to_shared(smu);
    int loK = (lane & 7) * KR_K + ((lane >> 3) & 1) * 4 + (lane >> 4) * 32;
    int loV = (lane & 7) * KR_V + ((lane >> 3) & 1) * 4 + (lane >> 4) * 64;

    // load slots (128 threads): K row = tid; V row = tid>>1, half (tid&1)*32
    int vrow = tid >> 1, vcb = (tid & 1) * 32;
    const uint32_t* khB = khp + kvh * 32;
    const uint32_t* klB = klp + kvh * 32;
    const uint32_t* vhB = vhp + (size_t)(kvh * HD + vrow) * (T_SEQ / 2) + vcb;
    const uint32_t* vlB = vlp + (size_t)(kvh * HD + vrow) * (T_SEQ / 2) + vcb;

    int kbmax = qb >> 1;

    // prefetch tile 0
    {
        uint32_t* Ks = smu;
        uint32_t* Vs = smu + KARR;
#pragma unroll
        for (int j = 0; j < 8; j++) {
            cp16u(Ks + tid * KR_K + j * 4,      khB + (size_t)tid * 128 + j * 4);
            cp16u(Ks + tid * KR_K + 32 + j * 4, klB + (size_t)tid * 128 + j * 4);
        }
#pragma unroll
        for (int j = 0; j < 8; j++) {
            cp16u(Vs + vrow * KR_V + vcb + j * 4,      vhB + j * 4);
            cp16u(Vs + vrow * KR_V + 64 + vcb + j * 4, vlB + j * 4);
        }
        asm volatile("cp.async.commit_group;");
    }

    float oacc[8][4];
#pragma unroll
    for (int nt = 0; nt < 8; nt++)
#pragma unroll
        for (int j = 0; j < 4; j++) oacc[nt][j] = 0.0f;
    float m0 = -1e30f, m1 = -1e30f, l0 = 0.0f, l1 = 0.0f;

    for (int kb = 0; kb <= kbmax; kb++) {
        asm volatile("cp.async.wait_group 0;");
        __syncthreads();   // tile kb visible to all warps

        uint32_t stK = smem_b + 4 * loK;
        uint32_t stV = smem_b + 4 * (KARR + loV);

        // ---- S = (Q/8) @ K^T : 3-term bf16 ----
        float sacc[16][4];
#pragma unroll
        for (int nt = 0; nt < 16; nt++)
#pragma unroll
            for (int j = 0; j < 4; j++) sacc[nt][j] = 0.0f;

#pragma unroll
        for (int nt = 0; nt < 16; nt++) {
            uint32_t rowa = stK + nt * (8 * KR_K * 4);
#pragma unroll
            for (int ks = 0; ks < 4; ks++) {
                uint32_t bh0, bh1, bl0, bl1;
                ldsm_x4(bh0, bh1, bl0, bl1, rowa + ks * 32);
                uint32_t bh[2] = {bh0, bh1}, bl[2] = {bl0, bl1};
                mma_bf16(sacc[nt], qhi[ks], bh, sacc[nt]);
                mma_bf16(sacc[nt], qlo[ks], bh, sacc[nt]);
                mma_bf16(sacc[nt], qhi[ks], bl, sacc[nt]);
            }
        }

        // ---- causal mask (last tile only) ----
        if (kb == kbmax) {
            int grow0 = qb * 64 + fr;
            int grow1 = grow0 + 8;
#pragma unroll
            for (int nt = 0; nt < 16; nt++) {
                int gc = kb * 128 + nt * 8 + tg2;
                if (gc     > grow0) sacc[nt][0] = -1e30f;
                if (gc + 1 > grow0) sacc[nt][1] = -1e30f;
                if (gc     > grow1) sacc[nt][2] = -1e30f;
                if (gc + 1 > grow1) sacc[nt][3] = -1e30f;
            }
        }

        // ---- online softmax ----
        float mx0 = -1e30f, mx1 = -1e30f;
#pragma unroll
        for (int nt = 0; nt < 16; nt++) {
            mx0 = fmaxf(mx0, fmaxf(sacc[nt][0], sacc[nt][1]));
            mx1 = fmaxf(mx1, fmaxf(sacc[nt][2], sacc[nt][3]));
        }
        mx0 = fmaxf(mx0, __shfl_xor_sync(0xffffffffu, mx0, 1));
        mx0 = fmaxf(mx0, __shfl_xor_sync(0xffffffffu, mx0, 2));
        mx1 = fmaxf(mx1, __shfl_xor_sync(0xffffffffu, mx1, 1));
        mx1 = fmaxf(mx1, __shfl_xor_sync(0xffffffffu, mx1, 2));

        float mn0 = fmaxf(m0, mx0), mn1 = fmaxf(m1, mx1);
        float c0 = __expf(m0 - mn0), c1 = __expf(m1 - mn1);
        float rs0 = 0.0f, rs1 = 0.0f;
#pragma unroll
        for (int nt = 0; nt < 16; nt++) {
            float p0 = __expf(sacc[nt][0] - mn0);
            float p1 = __expf(sacc[nt][1] - mn0);
            float p2 = __expf(sacc[nt][2] - mn1);
            float p3 = __expf(sacc[nt][3] - mn1);
            sacc[nt][0] = p0; sacc[nt][1] = p1;
            sacc[nt][2] = p2; sacc[nt][3] = p3;
            rs0 += p0 + p1;
            rs1 += p2 + p3;
        }
        rs0 += __shfl_xor_sync(0xffffffffu, rs0, 1);
        rs0 += __shfl_xor_sync(0xffffffffu, rs0, 2);
        rs1 += __shfl_xor_sync(0xffffffffu, rs1, 1);
        rs1 += __shfl_xor_sync(0xffffffffu, rs1, 2);
        l0 = l0 * c0 + rs0;  m0 = mn0;
        l1 = l1 * c1 + rs1;  m1 = mn1;
#pragma unroll
        for (int nt = 0; nt < 8; nt++) {
            oacc[nt][0] *= c0; oacc[nt][1] *= c0;
            oacc[nt][2] *= c1; oacc[nt][3] *= c1;
        }

        // ---- O += P @ V : A from sacc regs, B via ldmatrix ----
#pragma unroll
        for (int kt = 0; kt < 8; kt++) {
            uint32_t ahi[4], alo[4];
            splitbf(sacc[2*kt][0],     sacc[2*kt][1],     ahi[0], alo[0]);
            splitbf(sacc[2*kt][2],     sacc[2*kt][3],     ahi[1], alo[1]);
            splitbf(sacc[2*kt + 1][0], sacc[2*kt + 1][1], ahi[2], alo[2]);
            splitbf(sacc[2*kt + 1][2], sacc[2*kt + 1][3], ahi[3], alo[3]);
#pragma unroll
            for (int nt = 0; nt < 8; nt++) {
                uint32_t bh0, bh1, bl0, bl1;
                ldsm_x4(bh0, bh1, bl0, bl1,
                        stV + nt * (8 * KR_V * 4) + kt * 32);
                uint32_t bh[2] = {bh0, bh1}, bl[2] = {bl0, bl1};
                mma_bf16(oacc[nt], ahi, bh, oacc[nt]);
                mma_bf16(oacc[nt], alo, bh, oacc[nt]);
                mma_bf16(oacc[nt], ahi, bl, oacc[nt]);
            }
        }
        __syncthreads();   // all reads done before next prefetch overwrites

        if (kb < kbmax) {
            uint32_t* Ks = smu;
            uint32_t* Vs = smu + KARR;
            int tk = (kb + 1) * 128;
            int tv = (kb + 1) * 64;
#pragma unroll
            for (int j = 0; j < 8; j++) {
                cp16u(Ks + tid * KR_K + j * 4,
                      khB + (size_t)(tk + tid) * 128 + j * 4);
                cp16u(Ks + tid * KR_K + 32 + j * 4,
                      klB + (size_t)(tk + tid) * 128 + j * 4);
            }
#pragma unroll
            for (int j = 0; j < 8; j++) {
                cp16u(Vs + vrow * KR_V + vcb + j * 4,      vhB + tv + j * 4);
                cp16u(Vs + vrow * KR_V + 64 + vcb + j * 4, vlB + tv + j * 4);
            }
        }
        asm volatile("cp.async.commit_group;");
    }

    // ---- finalize ----
    float inv0 = 1.0f / l0, inv1 = 1.0f / l1;
#pragma unroll
    for (int nt = 0; nt < 8; nt++) {
        int col = h * HD + nt * 8 + tg2;
        float2 w0, w1;
        w0.x = roundtf(oacc[nt][0] * inv0); w0.y = roundtf(oacc[nt][1] * inv0);
        w1.x = roundtf(oacc[nt][2] * inv1); w1.y = roundtf(oacc[nt][3] * inv1);
        *(float2*)&op[(size_t)(qb * 64 + fr) * D_MODEL + col]     = w0;
        *(float2*)&op[(size_t)(qb * 64 + fr + 8) * D_MODEL + col] = w1;
    }
}

// ---------------- launch ---------------------------------------------------
extern "C" void kernel_launch(void* const* d_in, const int* in_sizes, int n_in,
                              void* d_out, int out_size)
{
    const float* X  = (const float*)d_in[0];
    const float* Wq = (const float*)d_in[1];
    const float* Wk = (const float*)d_in[2];
    const float* Wv = (const float*)d_in[3];
    const float* W1 = (const float*)d_in[4];
    const float* W2 = (const float*)d_in[5];
    float* out = (float*)d_out;

    float *gq, *gk, *gv, *ga, *gh;
    float *gxt, *gwqt, *gwkt, *gwvt, *gw1t, *gw2t;
    uint32_t *gkh, *gkl, *gvh, *gvl;
    cudaGetSymbolAddress((void**)&gq, g_q);
    cudaGetSymbolAddress((void**)&gk, g_k);
    cudaGetSymbolAddress((void**)&gv, g_v);
    cudaGetSymbolAddress((void**)&ga, g_attn);
    cudaGetSymbolAddress((void**)&gh, g_h1);
    cudaGetSymbolAddress((void**)&gxt, g_xt);
    cudaGetSymbolAddress((void**)&gwqt, g_wqt);
    cudaGetSymbolAddress((void**)&gwkt, g_wkt);
    cudaGetSymbolAddress((void**)&gwvt, g_wvt);
    cudaGetSymbolAddress((void**)&gw1t, g_w1t);
    cudaGetSymbolAddress((void**)&gw2t, g_w2t);
    cudaGetSymbolAddress((void**)&gkh, g_khp);
    cudaGetSymbolAddress((void**)&gkl, g_klp);
    cudaGetSymbolAddress((void**)&gvh, g_vhp);
    cudaGetSymbolAddress((void**)&gvl, g_vlp);

    cudaFuncSetAttribute(attn_bf16_kernel,
                         cudaFuncAttributeMaxDynamicSharedMemorySize, ATT_SMEM);
    cudaFuncSetAttribute(qkv_kernel,
                         cudaFuncAttributeMaxDynamicSharedMemorySize, GEMM_SMEM);
    cudaFuncSetAttribute(tgemm2_kernel<1, 1>,
                         cudaFuncAttributeMaxDynamicSharedMemorySize, GEMM_SMEM);
    cudaFuncSetAttribute(tgemm2_kernel<0, 0>,
                         cudaFuncAttributeMaxDynamicSharedMemorySize, GEMM_SMEM);

    round_all_kernel<<<13824, 256>>>(X, Wq, Wk, Wv, W1, W2);
    rope_table_kernel<<<T_SEQ, 32>>>();
    qkv_kernel<<<dim3(12, T_SEQ / 128), 256, GEMM_SMEM>>>(
        gxt, gwqt, gwkt, gwvt, gq, gk, gv);
    rope_apply_kernel<<<T_SEQ, NH * 32>>>(gq, NH);
    prep_kv_kernel<<<4096, 256>>>();
    attn_bf16_kernel<<<dim3(T_SEQ / 64, NH), 128, ATT_SMEM>>>(
        gq, gkh, gkl, gvh, gvl, ga);
    tgemm2_kernel<1, 1><<<dim3(D_FF / 128, T_SEQ / 128), 256, GEMM_SMEM>>>(
        ga, gw1t, gh, D_FF, D_MODEL);
    tgemm2_kernel<0, 0><<<dim3(D_MODEL / 128, T_SEQ / 128), 256, GEMM_SMEM>>>(
        gh, gw2t, out, D_MODEL, D_FF);
}

// round 14
// speedup vs baseline: 1.3482x; 1.3482x over previous
#include <cuda_runtime.h>
#include <cuda_bf16.h>
#include <math.h>
#include <stdint.h>

// Problem constants
#define T_SEQ  4096
#define D_MODEL 1024
#define NH     16
#define NKV    4
#define HD     64
#define D_FF   4096

// ---------------- scratch (device globals; no allocation allowed) ----------
__device__ float g_q[T_SEQ * D_MODEL];          // raw (pre-rope) Q
__device__ float g_k[T_SEQ * NKV * HD];         // [token][256] (pre-rope)
__device__ float g_v[NKV * HD * T_SEQ];         // TRANSPOSED [256][4096]
__device__ float g_attn[T_SEQ * D_MODEL];       // tf32-rounded
__device__ float g_h1[(size_t)T_SEQ * D_FF];    // tf32-rounded
__device__ float g_cos[T_SEQ * 32];
__device__ float g_sin[T_SEQ * 32];
__device__ float g_xt[T_SEQ * D_MODEL];
__device__ float g_wqt[D_MODEL * D_MODEL];
__device__ float g_wkt[D_MODEL * NKV * HD];
__device__ float g_wvt[D_MODEL * NKV * HD];
__device__ float g_w1t[D_MODEL * D_FF];
__device__ float g_w2t[D_FF * D_MODEL];
__device__ uint32_t g_khp[T_SEQ * 128];         // [token][kvh*32 + d2] bf16x2 hi
__device__ uint32_t g_klp[T_SEQ * 128];
__device__ uint32_t g_vhp[NKV * HD * (T_SEQ / 2)];  // [dim][token-pair]
__device__ uint32_t g_vlp[NKV * HD * (T_SEQ / 2)];

// ---------------- helpers ---------------------------------------------------
__device__ __forceinline__ uint32_t f2tf32(float x) {
    uint32_t r;
    asm("cvt.rna.tf32.f32 %0, %1;" : "=r"(r) : "f"(x));
    return r;
}
__device__ __forceinline__ float roundtf(float x) {
    return __uint_as_float(f2tf32(x));
}

__device__ __forceinline__ void mma_tf32(float* d, const uint32_t* a,
                                         const uint32_t* b, const float* c) {
    asm volatile(
        "mma.sync.aligned.m16n8k8.row.col.f32.tf32.tf32.f32 "
        "{%0,%1,%2,%3}, {%4,%5,%6,%7}, {%8,%9}, {%10,%11,%12,%13};"
        : "=f"(d[0]), "=f"(d[1]), "=f"(d[2]), "=f"(d[3])
        : "r"(a[0]), "r"(a[1]), "r"(a[2]), "r"(a[3]),
          "r"(b[0]), "r"(b[1]),
          "f"(c[0]), "f"(c[1]), "f"(c[2]), "f"(c[3]));
}

__device__ __forceinline__ void mma_bf16(float* d, const uint32_t* a,
                                         const uint32_t* b, const float* c) {
    asm volatile(
        "mma.sync.aligned.m16n8k16.row.col.f32.bf16.bf16.f32 "
        "{%0,%1,%2,%3}, {%4,%5,%6,%7}, {%8,%9}, {%10,%11,%12,%13};"
        : "=f"(d[0]), "=f"(d[1]), "=f"(d[2]), "=f"(d[3])
        : "r"(a[0]), "r"(a[1]), "r"(a[2]), "r"(a[3]),
          "r"(b[0]), "r"(b[1]),
          "f"(c[0]), "f"(c[1]), "f"(c[2]), "f"(c[3]));
}

__device__ __forceinline__ void ldsm_x4(uint32_t& r0, uint32_t& r1,
                                        uint32_t& r2, uint32_t& r3,
                                        uint32_t saddr) {
    asm volatile(
        "ldmatrix.sync.aligned.m8n8.x4.shared.b16 {%0,%1,%2,%3}, [%4];"
        : "=r"(r0), "=r"(r1), "=r"(r2), "=r"(r3) : "r"(saddr));
}

__device__ __forceinline__ uint32_t packbf(float x, float y) {
    __nv_bfloat162 t = __floats2bfloat162_rn(x, y);
    return *(uint32_t*)&t;
}
__device__ __forceinline__ void splitbf(float x, float y,
                                        uint32_t& hi, uint32_t& lo) {
    __nv_bfloat16 hx = __float2bfloat16_rn(x);
    __nv_bfloat16 hy = __float2bfloat16_rn(y);
    hi = packbf(__bfloat162float(hx), __bfloat162float(hy));
    lo = packbf(x - __bfloat162float(hx), y - __bfloat162float(hy));
}

__device__ __forceinline__ void cp16(float* smem_dst, const float* g) {
    uint32_t a = (uint32_t)__cvta_generic_to_shared(smem_dst);
    asm volatile("cp.async.ca.shared.global [%0], [%1], 16;" :: "r"(a), "l"(g));
}
__device__ __forceinline__ void cp16u(uint32_t* smem_dst, const uint32_t* g) {
    uint32_t a = (uint32_t)__cvta_generic_to_shared(smem_dst);
    asm volatile("cp.async.ca.shared.global [%0], [%1], 16;" :: "r"(a), "l"(g));
}

// ---------------- merged pre-round pass -------------------------------------
// Segments (float4-blocks of 256):
//   X 4096 | Wq 1024 | Wk 256 | Wv 256 | W1 4096 | W2 4096 => 13824 blocks
__global__ void round_all_kernel(
    const float* __restrict__ X,  const float* __restrict__ Wq,
    const float* __restrict__ Wk, const float* __restrict__ Wv,
    const float* __restrict__ W1, const float* __restrict__ W2)
{
    int b = blockIdx.x;
    const float* src;
    float* dst;
    int base;
    if      (b < 4096) { src = X;  dst = g_xt;  base = 0;    }
    else if (b < 5120) { src = Wq; dst = g_wqt; base = 4096; }
    else if (b < 5376) { src = Wk; dst = g_wkt; base = 5120; }
    else if (b < 5632) { src = Wv; dst = g_wvt; base = 5376; }
    else if (b < 9728) { src = W1; dst = g_w1t; base = 5632; }
    else               { src = W2; dst = g_w2t; base = 9728; }
    int i = (b - base) * 256 + threadIdx.x;
    float4 v = ((const float4*)src)[i];
    v.x = roundtf(v.x); v.y = roundtf(v.y);
    v.z = roundtf(v.z); v.w = roundtf(v.w);
    ((float4*)dst)[i] = v;
}

// ---------------- RoPE table ------------------------------------------------
__global__ void rope_table_kernel() {
    int t = blockIdx.x, i = threadIdx.x;
    float inv = 1.0f / powf(10000.0f, (float)(2 * i) / 64.0f);
    float ang = (float)t * inv;
    g_cos[t * 32 + i] = cosf(ang);
    g_sin[t * 32 + i] = sinf(ang);
}

// ---------------- fused KV prep ---------------------------------------------
__global__ void prep_kv_kernel() {
    int b = blockIdx.x;
    if (b < 2048) {
        __shared__ float buf[2][NKV][64];
        int sub = threadIdx.x >> 7;
        int wt  = threadIdx.x & 127;
        int t = b * 2 + sub;
        int h = wt >> 5;
        int i = wt & 31;
        float c = g_cos[t * 32 + i];
        float s = g_sin[t * 32 + i];
        const float* p = g_k + (size_t)t * (NKV * HD) + h * HD;
        float x1 = p[i], x2 = p[i + 32];
        buf[sub][h][i]      = x1 * c - x2 * s;
        buf[sub][h][i + 32] = x2 * c + x1 * s;
        __syncthreads();
        float a = buf[sub][h][2 * i], bb = buf[sub][h][2 * i + 1];
        uint32_t hi, lo;
        splitbf(a, bb, hi, lo);
        g_khp[t * 128 + h * 32 + i] = hi;
        g_klp[t * 128 + h * 32 + i] = lo;
    } else {
        int idx = (b - 2048) * 256 + threadIdx.x;
        float2 v = *(const float2*)&g_v[(size_t)idx * 2];
        uint32_t hi, lo;
        splitbf(v.x, v.y, hi, lo);
        g_vhp[idx] = hi;
        g_vlp[idx] = lo;
    }
}

// ---------------- cp.async tf32 GEMM (R10 proven: BK=16, 4-stage, ldsm A) ---
#define AS_ST 20
#define BS_ST 136
#define AS_STAGE (128 * AS_ST)
#define BS_STAGE (16 * BS_ST)
#define GEMM_SMEM ((4 * (AS_STAGE + BS_STAGE)) * 4)

template <int SILU, int ROUND, int TRANSC>
__device__ __forceinline__ void gemm_body(
    const float* __restrict__ A, const float* __restrict__ B,
    float* __restrict__ C, int N, int K, int rowBase, int colBase)
{
    extern __shared__ float smp[];
    float* As = smp;
    float* Bs = smp + 4 * AS_STAGE;

    int tid  = threadIdx.x;
    int lane = tid & 31;
    int warp = tid >> 5;
    int wm = (warp & 1) * 64;
    int wn = (warp >> 1) * 32;

    int ar  = tid >> 2;
    int ac  = (tid & 3) << 2;
    int bkr = tid >> 5;
    int bc  = (tid & 31) << 2;

    const float* Ag0 = A + (size_t)(rowBase + ar) * K + ac;
    const float* Ag1 = A + (size_t)(rowBase + 64 + ar) * K + ac;
    const float* Bg  = B + colBase + bc;

    uint32_t smem_b = (uint32_t)__cvta_generic_to_shared(smp);
    uint32_t loA = ((wm + (lane & 7) + ((lane >> 3) & 1) * 8) * AS_ST
                    + (lane >> 4) * 4) * 4;

    int nk = K >> 4;

#pragma unroll
    for (int s = 0; s < 3; s++) {
        if (s < nk) {
            float* as = As + s * AS_STAGE;
            float* bs = Bs + s * BS_STAGE;
            int k0 = s << 4;
            cp16(as + ar * AS_ST + ac,        Ag0 + k0);
            cp16(as + (ar + 64) * AS_ST + ac, Ag1 + k0);
            cp16(bs + bkr * BS_ST + bc,       Bg + (size_t)(k0 + bkr) * N);
            cp16(bs + (bkr + 8) * BS_ST + bc, Bg + (size_t)(k0 + 8 + bkr) * N);
        }
        asm volatile("cp.async.commit_group;");
    }

    float acc[4][4][4];
#pragma unroll
    for (int i = 0; i < 4; i++)
#pragma unroll
        for (int j = 0; j < 4; j++)
#pragma unroll
            for (int q = 0; q < 4; q++) acc[i][j][q] = 0.0f;

    for (int kt = 0; kt < nk; kt++) {
        asm volatile("cp.async.wait_group 2;");
        __syncthreads();

        int nx = kt + 3;
        if (nx < nk) {
            int bufn = nx & 3;
            float* as = As + bufn * AS_STAGE;
            float* bs = Bs + bufn * BS_STAGE;
            int k0 = nx << 4;
            cp16(as + ar * AS_ST + ac,        Ag0 + k0);
            cp16(as + (ar + 64) * AS_ST + ac, Ag1 + k0);
            cp16(bs + bkr * BS_ST + bc,       Bg + (size_t)(k0 + bkr) * N);
            cp16(bs + (bkr + 8) * BS_ST + bc, Bg + (size_t)(k0 + 8 + bkr) * N);
        }
        asm volatile("cp.async.commit_group;");

        uint32_t asb = smem_b + ((kt & 3) * AS_STAGE) * 4 + loA;
        const float* bs = Bs + (kt & 3) * BS_STAGE;
#pragma unroll
        for (int ks = 0; ks < 16; ks += 8) {
            uint32_t af[4][4], bf[4][2];
#pragma unroll
            for (int i = 0; i < 4; i++) {
                ldsm_x4(af[i][0], af[i][1], af[i][2], af[i][3],
                        asb + (i * 16 * AS_ST + ks) * 4);
            }
#pragma unroll
            for (int j = 0; j < 4; j++) {
                int kk = ks + (lane & 3);
                int n  = wn + j * 8 + (lane >> 2);
                bf[j][0] = __float_as_uint(bs[kk * BS_ST + n]);
                bf[j][1] = __float_as_uint(bs[(kk + 4) * BS_ST + n]);
            }
#pragma unroll
            for (int i = 0; i < 4; i++)
#pragma unroll
                for (int j = 0; j < 4; j++)
                    mma_tf32(acc[i][j], af[i], bf[j], acc[i][j]);
        }
    }

#pragma unroll
    for (int i = 0; i < 4; i++) {
        int r0 = rowBase + wm + i * 16 + (lane >> 2);
#pragma unroll
        for (int j = 0; j < 4; j++) {
            int c0 = colBase + wn + j * 8 + (lane & 3) * 2;
            float2 v0, v1;
            v0.x = acc[i][j][0]; v0.y = acc[i][j][1];
            v1.x = acc[i][j][2]; v1.y = acc[i][j][3];
            if (SILU) {
                v0.x = v0.x / (1.0f + expf(-v0.x));
                v0.y = v0.y / (1.0f + expf(-v0.y));
                v1.x = v1.x / (1.0f + expf(-v1.x));
                v1.y = v1.y / (1.0f + expf(-v1.y));
            }
            if (ROUND) {
                v0.x = roundtf(v0.x); v0.y = roundtf(v0.y);
                v1.x = roundtf(v1.x); v1.y = roundtf(v1.y);
            }
            if (TRANSC) {
                C[(size_t)c0 * T_SEQ + r0]           = v0.x;
                C[(size_t)(c0 + 1) * T_SEQ + r0]     = v0.y;
                C[(size_t)c0 * T_SEQ + r0 + 8]       = v1.x;
                C[(size_t)(c0 + 1) * T_SEQ + r0 + 8] = v1.y;
            } else {
                *(float2*)&C[(size_t)r0 * N + c0]       = v0;
                *(float2*)&C[(size_t)(r0 + 8) * N + c0] = v1;
            }
        }
    }
}

template <int SILU, int ROUND>
__global__ void __launch_bounds__(256, 2) tgemm2_kernel(
    const float* __restrict__ A, const float* __restrict__ B,
    float* __restrict__ C, int N, int K)
{
    gemm_body<SILU, ROUND, 0>(A, B, C, N, K, blockIdx.y * 128, blockIdx.x * 128);
}

__global__ void __launch_bounds__(256, 2) qkv_kernel(
    const float* __restrict__ Xt,
    const float* __restrict__ Wqt, const float* __restrict__ Wkt,
    const float* __restrict__ Wvt,
    float* __restrict__ q, float* __restrict__ k, float* __restrict__ v)
{
    int bx = blockIdx.x;
    if (bx < 8) {
        gemm_body<0, 0, 0>(Xt, Wqt, q, D_MODEL, D_MODEL,
                           blockIdx.y * 128, bx * 128);
    } else if (bx < 10) {
        gemm_body<0, 0, 0>(Xt, Wkt, k, NKV * HD, D_MODEL,
                           blockIdx.y * 128, (bx - 8) * 128);
    } else {
        gemm_body<0, 0, 1>(Xt, Wvt, v, NKV * HD, D_MODEL,
                           blockIdx.y * 128, (bx - 10) * 128);
    }
}

// ---------------- bf16 MMA flash attention (BM=128, BN=128) ----------------
// RoPE on Q fused into Q-staging (raw Q in, rope applied in smem).
#define KR_K 68
#define KR_V 132
#define KARR (128 * KR_K)           // 8704 u32
#define VARR (64 * KR_V)            // 8448 u32
#define STAGE_U (KARR + VARR)       // 17152 u32
#define ATT_SMEM (2 * STAGE_U * 4)  // 137216 bytes

__global__ void __launch_bounds__(256) attn_bf16_kernel(
    const float* __restrict__ qp,
    const uint32_t* __restrict__ khp, const uint32_t* __restrict__ klp,
    const uint32_t* __restrict__ vhp, const uint32_t* __restrict__ vlp,
    float* __restrict__ op)
{
    extern __shared__ uint32_t smu[];
    float* Qs = (float*)smu;

    int qb   = gridDim.x - 1 - blockIdx.x;
    int h    = blockIdx.y;
    int kvh  = h >> 2;
    int tid  = threadIdx.x;
    int lane = tid & 31;
    int warp = tid >> 5;
    int gid  = lane >> 2;
    int tig  = lane & 3;
    int tg2  = tig * 2;
    int fr   = warp * 16 + gid;

    // ---- stage raw Q tile ----
#pragma unroll
    for (int i = 0; i < 8; i++) {
        int e = tid + 256 * i;
        int r = e >> 4, c4 = (e & 15) << 2;
        *(float4*)&Qs[r * 64 + c4] =
            *(const float4*)&qp[(size_t)(qb * 128 + r) * D_MODEL + h * HD + c4];
    }
    __syncthreads();

    // ---- in-place RoPE: 128 rows x 32 pairs = 4096 pairs, 16/thread ----
#pragma unroll
    for (int it = 0; it < 16; it++) {
        int p = tid + 256 * it;
        int r = p >> 5, i = p & 31;
        float c = g_cos[(qb * 128 + r) * 32 + i];
        float s = g_sin[(qb * 128 + r) * 32 + i];
        float x1 = Qs[r * 64 + i], x2 = Qs[r * 64 + i + 32];
        Qs[r * 64 + i]      = x1 * c - x2 * s;
        Qs[r * 64 + i + 32] = x2 * c + x1 * s;
    }
    __syncthreads();

    uint32_t qhi[4][4], qlo[4][4];
#pragma unroll
    for (int kt = 0; kt < 4; kt++) {
        float2 x0 = *(float2*)&Qs[fr * 64 + kt * 16 + tg2];
        float2 x1 = *(float2*)&Qs[(fr + 8) * 64 + kt * 16 + tg2];
        float2 x2 = *(float2*)&Qs[fr * 64 + kt * 16 + tg2 + 8];
        float2 x3 = *(float2*)&Qs[(fr + 8) * 64 + kt * 16 + tg2 + 8];
        splitbf(x0.x * 0.125f, x0.y * 0.125f, qhi[kt][0], qlo[kt][0]);
        splitbf(x1.x * 0.125f, x1.y * 0.125f, qhi[kt][1], qlo[kt][1]);
        splitbf(x2.x * 0.125f, x2.y * 0.125f, qhi[kt][2], qlo[kt][2]);
        splitbf(x3.x * 0.125f, x3.y * 0.125f, qhi[kt][3], qlo[kt][3]);
    }
    __syncthreads();   // Q reads done before cp.async overwrites stage 0

    uint32_t smem_b = (uint32_t)__cvta_generic_to_shared(smu);
    int loK = (lane & 7) * KR_K + ((lane >> 3) & 1) * 4 + (lane >> 4) * 32;
    int loV = (lane & 7) * KR_V + ((lane >> 3) & 1) * 4 + (lane >> 4) * 64;

    int rK = tid >> 1, hK = (tid & 1) * 16;
    int rV = tid >> 2, qV = (tid & 3) * 16;
    const uint32_t* khB = khp + kvh * 32;
    const uint32_t* klB = klp + kvh * 32;
    const uint32_t* vhB = vhp + (size_t)(kvh * HD + rV) * (T_SEQ / 2);
    const uint32_t* vlB = vlp + (size_t)(kvh * HD + rV) * (T_SEQ / 2);

    int kbmax = qb;

    {
        uint32_t* Ks = smu;
        uint32_t* Vs = smu + KARR;
#pragma unroll
        for (int j = 0; j < 4; j++) {
            int c = hK + j * 4;
            cp16u(Ks + rK * KR_K + c,      khB + (size_t)rK * 128 + c);
            cp16u(Ks + rK * KR_K + 32 + c, klB + (size_t)rK * 128 + c);
        }
#pragma unroll
        for (int j = 0; j < 4; j++) {
            int c = qV + j * 4;
            cp16u(Vs + rV * KR_V + c,      vhB + c);
            cp16u(Vs + rV * KR_V + 64 + c, vlB + c);
        }
        asm volatile("cp.async.commit_group;");
    }

    float oacc[8][4];
#pragma unroll
    for (int nt = 0; nt < 8; nt++)
#pragma unroll
        for (int j = 0; j < 4; j++) oacc[nt][j] = 0.0f;
    float m0 = -1e30f, m1 = -1e30f, l0 = 0.0f, l1 = 0.0f;

    for (int kb = 0; kb <= kbmax; kb++) {
        asm volatile("cp.async.wait_group 0;");
        __syncthreads();

        if (kb < kbmax) {
            uint32_t* st = smu + ((kb + 1) & 1) * STAGE_U;
            uint32_t* Ks = st;
            uint32_t* Vs = st + KARR;
            int tk = (kb + 1) * 128;
            int tv = (kb + 1) * 64;
#pragma unroll
            for (int j = 0; j < 4; j++) {
                int c = hK + j * 4;
                cp16u(Ks + rK * KR_K + c,      khB + (size_t)(tk + rK) * 128 + c);
                cp16u(Ks + rK * KR_K + 32 + c, klB + (size_t)(tk + rK) * 128 + c);
            }
#pragma unroll
            for (int j = 0; j < 4; j++) {
                int c = qV + j * 4;
                cp16u(Vs + rV * KR_V + c,      vhB + tv + c);
                cp16u(Vs + rV * KR_V + 64 + c, vlB + tv + c);
            }
        }
        asm volatile("cp.async.commit_group;");

        uint32_t stK = smem_b + 4 * ((kb & 1) * STAGE_U + loK);
        uint32_t stV = smem_b + 4 * ((kb & 1) * STAGE_U + KARR + loV);

        float sacc[16][4];
#pragma unroll
        for (int nt = 0; nt < 16; nt++)
#pragma unroll
            for (int j = 0; j < 4; j++) sacc[nt][j] = 0.0f;

#pragma unroll
        for (int nt = 0; nt < 16; nt++) {
            uint32_t rowa = stK + nt * (8 * KR_K * 4);
#pragma unroll
            for (int ks = 0; ks < 4; ks++) {
                uint32_t bh0, bh1, bl0, bl1;
                ldsm_x4(bh0, bh1, bl0, bl1, rowa + ks * 32);
                uint32_t bh[2] = {bh0, bh1}, bl[2] = {bl0, bl1};
                mma_bf16(sacc[nt], qhi[ks], bh, sacc[nt]);
                mma_bf16(sacc[nt], qlo[ks], bh, sacc[nt]);
                mma_bf16(sacc[nt], qhi[ks], bl, sacc[nt]);
            }
        }

        if (kb == qb) {
            int grow0 = qb * 128 + fr;
            int grow1 = grow0 + 8;
#pragma unroll
            for (int nt = 0; nt < 16; nt++) {
                int gc = kb * 128 + nt * 8 + tg2;
                if (gc     > grow0) sacc[nt][0] = -1e30f;
                if (gc + 1 > grow0) sacc[nt][1] = -1e30f;
                if (gc     > grow1) sacc[nt][2] = -1e30f;
                if (gc + 1 > grow1) sacc[nt][3] = -1e30f;
            }
        }

        float mx0 = -1e30f, mx1 = -1e30f;
#pragma unroll
        for (int nt = 0; nt < 16; nt++) {
            mx0 = fmaxf(mx0, fmaxf(sacc[nt][0], sacc[nt][1]));
            mx1 = fmaxf(mx1, fmaxf(sacc[nt][2], sacc[nt][3]));
        }
        mx0 = fmaxf(mx0, __shfl_xor_sync(0xffffffffu, mx0, 1));
        mx0 = fmaxf(mx0, __shfl_xor_sync(0xffffffffu, mx0, 2));
        mx1 = fmaxf(mx1, __shfl_xor_sync(0xffffffffu, mx1, 1));
        mx1 = fmaxf(mx1, __shfl_xor_sync(0xffffffffu, mx1, 2));

        float mn0 = fmaxf(m0, mx0), mn1 = fmaxf(m1, mx1);
        float c0 = __expf(m0 - mn0), c1 = __expf(m1 - mn1);
        float rs0 = 0.0f, rs1 = 0.0f;
#pragma unroll
        for (int nt = 0; nt < 16; nt++) {
            float p0 = __expf(sacc[nt][0] - mn0);
            float p1 = __expf(sacc[nt][1] - mn0);
            float p2 = __expf(sacc[nt][2] - mn1);
            float p3 = __expf(sacc[nt][3] - mn1);
            sacc[nt][0] = p0; sacc[nt][1] = p1;
            sacc[nt][2] = p2; sacc[nt][3] = p3;
            rs0 += p0 + p1;
            rs1 += p2 + p3;
        }
        rs0 += __shfl_xor_sync(0xffffffffu, rs0, 1);
        rs0 += __shfl_xor_sync(0xffffffffu, rs0, 2);
        rs1 += __shfl_xor_sync(0xffffffffu, rs1, 1);
        rs1 += __shfl_xor_sync(0xffffffffu, rs1, 2);
        l0 = l0 * c0 + rs0;  m0 = mn0;
        l1 = l1 * c1 + rs1;  m1 = mn1;
#pragma unroll
        for (int nt = 0; nt < 8; nt++) {
            oacc[nt][0] *= c0; oacc[nt][1] *= c0;
            oacc[nt][2] *= c1; oacc[nt][3] *= c1;
        }

#pragma unroll
        for (int kt = 0; kt < 8; kt++) {
            uint32_t ahi[4], alo[4];
            splitbf(sacc[2*kt][0],     sacc[2*kt][1],     ahi[0], alo[0]);
            splitbf(sacc[2*kt][2],     sacc[2*kt][3],     ahi[1], alo[1]);
            splitbf(sacc[2*kt + 1][0], sacc[2*kt + 1][1], ahi[2], alo[2]);
            splitbf(sacc[2*kt + 1][2], sacc[2*kt + 1][3], ahi[3], alo[3]);
#pragma unroll
            for (int nt = 0; nt < 8; nt++) {
                uint32_t bh0, bh1, bl0, bl1;
                ldsm_x4(bh0, bh1, bl0, bl1,
                        stV + nt * (8 * KR_V * 4) + kt * 32);
                uint32_t bh[2] = {bh0, bh1}, bl[2] = {bl0, bl1};
                mma_bf16(oacc[nt], ahi, bh, oacc[nt]);
                mma_bf16(oacc[nt], alo, bh, oacc[nt]);
                mma_bf16(oacc[nt], ahi, bl, oacc[nt]);
            }
        }
    }

    float inv0 = 1.0f / l0, inv1 = 1.0f / l1;
#pragma unroll
    for (int nt = 0; nt < 8; nt++) {
        int col = h * HD + nt * 8 + tg2;
        float2 w0, w1;
        w0.x = roundtf(oacc[nt][0] * inv0); w0.y = roundtf(oacc[nt][1] * inv0);
        w1.x = roundtf(oacc[nt][2] * inv1); w1.y = roundtf(oacc[nt][3] * inv1);
        *(float2*)&op[(size_t)(qb * 128 + fr) * D_MODEL + col]     = w0;
        *(float2*)&op[(size_t)(qb * 128 + fr + 8) * D_MODEL + col] = w1;
    }
}

// ---------------- launch ---------------------------------------------------
extern "C" void kernel_launch(void* const* d_in, const int* in_sizes, int n_in,
                              void* d_out, int out_size)
{
    const float* X  = (const float*)d_in[0];
    const float* Wq = (const float*)d_in[1];
    const float* Wk = (const float*)d_in[2];
    const float* Wv = (const float*)d_in[3];
    const float* W1 = (const float*)d_in[4];
    const float* W2 = (const float*)d_in[5];
    float* out = (float*)d_out;

    float *gq, *gk, *gv, *ga, *gh;
    float *gxt, *gwqt, *gwkt, *gwvt, *gw1t, *gw2t;
    uint32_t *gkh, *gkl, *gvh, *gvl;
    cudaGetSymbolAddress((void**)&gq, g_q);
    cudaGetSymbolAddress((void**)&gk, g_k);
    cudaGetSymbolAddress((void**)&gv, g_v);
    cudaGetSymbolAddress((void**)&ga, g_attn);
    cudaGetSymbolAddress((void**)&gh, g_h1);
    cudaGetSymbolAddress((void**)&gxt, g_xt);
    cudaGetSymbolAddress((void**)&gwqt, g_wqt);
    cudaGetSymbolAddress((void**)&gwkt, g_wkt);
    cudaGetSymbolAddress((void**)&gwvt, g_wvt);
    cudaGetSymbolAddress((void**)&gw1t, g_w1t);
    cudaGetSymbolAddress((void**)&gw2t, g_w2t);
    cudaGetSymbolAddress((void**)&gkh, g_khp);
    cudaGetSymbolAddress((void**)&gkl, g_klp);
    cudaGetSymbolAddress((void**)&gvh, g_vhp);
    cudaGetSymbolAddress((void**)&gvl, g_vlp);

    cudaFuncSetAttribute(attn_bf16_kernel,
                         cudaFuncAttributeMaxDynamicSharedMemorySize, ATT_SMEM);
    cudaFuncSetAttribute(qkv_kernel,
                         cudaFuncAttributeMaxDynamicSharedMemorySize, GEMM_SMEM);
    cudaFuncSetAttribute(tgemm2_kernel<1, 1>,
                         cudaFuncAttributeMaxDynamicSharedMemorySize, GEMM_SMEM);
    cudaFuncSetAttribute(tgemm2_kernel<0, 0>,
                         cudaFuncAttributeMaxDynamicSharedMemorySize, GEMM_SMEM);

    round_all_kernel<<<13824, 256>>>(X, Wq, Wk, Wv, W1, W2);
    rope_table_kernel<<<T_SEQ, 32>>>();
    qkv_kernel<<<dim3(12, T_SEQ / 128), 256, GEMM_SMEM>>>(
        gxt, gwqt, gwkt, gwvt, gq, gk, gv);
    prep_kv_kernel<<<4096, 256>>>();
    attn_bf16_kernel<<<dim3(T_SEQ / 128, NH), 256, ATT_SMEM>>>(
        gq, gkh, gkl, gvh, gvl, ga);
    tgemm2_kernel<1, 1><<<dim3(D_FF / 128, T_SEQ / 128), 256, GEMM_SMEM>>>(
        ga, gw1t, gh, D_FF, D_MODEL);
    tgemm2_kernel<0, 0><<<dim3(D_MODEL / 128, T_SEQ / 128), 256, GEMM_SMEM>>>(
        gh, gw2t, out, D_MODEL, D_FF);
}

// round 15
// speedup vs baseline: 1.3533x; 1.0038x over previous
#include <cuda_runtime.h>
#include <cuda_bf16.h>
#include <math.h>
#include <stdint.h>

// Problem constants
#define T_SEQ  4096
#define D_MODEL 1024
#define NH     16
#define NKV    4
#define HD     64
#define D_FF   4096

// ---------------- scratch (device globals; no allocation allowed) ----------
__device__ float g_q[T_SEQ * D_MODEL];          // raw (pre-rope) Q
__device__ float g_k[T_SEQ * NKV * HD];         // [token][256] (pre-rope)
__device__ float g_v[NKV * HD * T_SEQ];         // TRANSPOSED [256][4096]
__device__ float g_attn[T_SEQ * D_MODEL];       // tf32-rounded
__device__ float g_h1[(size_t)T_SEQ * D_FF];    // tf32-rounded
__device__ float g_cos[T_SEQ * 32];
__device__ float g_sin[T_SEQ * 32];
__device__ float g_xt[T_SEQ * D_MODEL];
__device__ float g_wqt[D_MODEL * D_MODEL];
__device__ float g_wkt[D_MODEL * NKV * HD];
__device__ float g_wvt[D_MODEL * NKV * HD];
__device__ float g_w1t[D_MODEL * D_FF];
__device__ float g_w2t[D_FF * D_MODEL];
__device__ uint32_t g_khp[T_SEQ * 128];         // [token][kvh*32 + d2] bf16x2 hi
__device__ uint32_t g_klp[T_SEQ * 128];
__device__ uint32_t g_vhp[NKV * HD * (T_SEQ / 2)];  // [dim][token-pair]
__device__ uint32_t g_vlp[NKV * HD * (T_SEQ / 2)];

// ---------------- helpers ---------------------------------------------------
__device__ __forceinline__ uint32_t f2tf32(float x) {
    uint32_t r;
    asm("cvt.rna.tf32.f32 %0, %1;" : "=r"(r) : "f"(x));
    return r;
}
__device__ __forceinline__ float roundtf(float x) {
    return __uint_as_float(f2tf32(x));
}

__device__ __forceinline__ void mma_tf32(float* d, const uint32_t* a,
                                         const uint32_t* b, const float* c) {
    asm volatile(
        "mma.sync.aligned.m16n8k8.row.col.f32.tf32.tf32.f32 "
        "{%0,%1,%2,%3}, {%4,%5,%6,%7}, {%8,%9}, {%10,%11,%12,%13};"
        : "=f"(d[0]), "=f"(d[1]), "=f"(d[2]), "=f"(d[3])
        : "r"(a[0]), "r"(a[1]), "r"(a[2]), "r"(a[3]),
          "r"(b[0]), "r"(b[1]),
          "f"(c[0]), "f"(c[1]), "f"(c[2]), "f"(c[3]));
}

__device__ __forceinline__ void mma_bf16(float* d, const uint32_t* a,
                                         const uint32_t* b, const float* c) {
    asm volatile(
        "mma.sync.aligned.m16n8k16.row.col.f32.bf16.bf16.f32 "
        "{%0,%1,%2,%3}, {%4,%5,%6,%7}, {%8,%9}, {%10,%11,%12,%13};"
        : "=f"(d[0]), "=f"(d[1]), "=f"(d[2]), "=f"(d[3])
        : "r"(a[0]), "r"(a[1]), "r"(a[2]), "r"(a[3]),
          "r"(b[0]), "r"(b[1]),
          "f"(c[0]), "f"(c[1]), "f"(c[2]), "f"(c[3]));
}

__device__ __forceinline__ void ldsm_x4(uint32_t& r0, uint32_t& r1,
                                        uint32_t& r2, uint32_t& r3,
                                        uint32_t saddr) {
    asm volatile(
        "ldmatrix.sync.aligned.m8n8.x4.shared.b16 {%0,%1,%2,%3}, [%4];"
        : "=r"(r0), "=r"(r1), "=r"(r2), "=r"(r3) : "r"(saddr));
}

__device__ __forceinline__ uint32_t packbf(float x, float y) {
    __nv_bfloat162 t = __floats2bfloat162_rn(x, y);
    return *(uint32_t*)&t;
}
__device__ __forceinline__ void splitbf(float x, float y,
                                        uint32_t& hi, uint32_t& lo) {
    __nv_bfloat16 hx = __float2bfloat16_rn(x);
    __nv_bfloat16 hy = __float2bfloat16_rn(y);
    hi = packbf(__bfloat162float(hx), __bfloat162float(hy));
    lo = packbf(x - __bfloat162float(hx), y - __bfloat162float(hy));
}

__device__ __forceinline__ void cp16(float* smem_dst, const float* g) {
    uint32_t a = (uint32_t)__cvta_generic_to_shared(smem_dst);
    asm volatile("cp.async.ca.shared.global [%0], [%1], 16;" :: "r"(a), "l"(g));
}
__device__ __forceinline__ void cp16u(uint32_t* smem_dst, const uint32_t* g) {
    uint32_t a = (uint32_t)__cvta_generic_to_shared(smem_dst);
    asm volatile("cp.async.ca.shared.global [%0], [%1], 16;" :: "r"(a), "l"(g));
}

// ---------------- merged pre-round + rope-table pass ------------------------
// Chunks of 1024 float4 (4 per thread, stride 256):
//   X 1024 | Wq 256 | Wk 64 | Wv 64 | W1 1024 | W2 1024 = 3456 chunks
// Blocks [3456, 3968): rope cos/sin table (131072 angles).
__global__ void round_all_kernel(
    const float* __restrict__ X,  const float* __restrict__ Wq,
    const float* __restrict__ Wk, const float* __restrict__ Wv,
    const float* __restrict__ W1, const float* __restrict__ W2)
{
    int b = blockIdx.x;
    if (b >= 3456) {
        int idx = (b - 3456) * 256 + threadIdx.x;   // 0..131071 == t*32 + i
        int i = idx & 31;
        float inv = 1.0f / powf(10000.0f, (float)(2 * i) / 64.0f);
        float ang = (float)(idx >> 5) * inv;
        g_cos[idx] = cosf(ang);
        g_sin[idx] = sinf(ang);
        return;
    }
    const float* src;
    float* dst;
    int base;
    if      (b < 1024) { src = X;  dst = g_xt;  base = 0;    }
    else if (b < 1280) { src = Wq; dst = g_wqt; base = 1024; }
    else if (b < 1344) { src = Wk; dst = g_wkt; base = 1280; }
    else if (b < 1408) { src = Wv; dst = g_wvt; base = 1344; }
    else if (b < 2432) { src = W1; dst = g_w1t; base = 1408; }
    else               { src = W2; dst = g_w2t; base = 2432; }
    size_t off = (size_t)(b - base) * 1024 + threadIdx.x;
#pragma unroll
    for (int j = 0; j < 4; j++) {
        float4 v = ((const float4*)src)[off + j * 256];
        v.x = roundtf(v.x); v.y = roundtf(v.y);
        v.z = roundtf(v.z); v.w = roundtf(v.w);
        ((float4*)dst)[off + j * 256] = v;
    }
}

// ---------------- fused KV prep ---------------------------------------------
__global__ void prep_kv_kernel() {
    int b = blockIdx.x;
    if (b < 2048) {
        __shared__ float buf[2][NKV][64];
        int sub = threadIdx.x >> 7;
        int wt  = threadIdx.x & 127;
        int t = b * 2 + sub;
        int h = wt >> 5;
        int i = wt & 31;
        float c = g_cos[t * 32 + i];
        float s = g_sin[t * 32 + i];
        const float* p = g_k + (size_t)t * (NKV * HD) + h * HD;
        float x1 = p[i], x2 = p[i + 32];
        buf[sub][h][i]      = x1 * c - x2 * s;
        buf[sub][h][i + 32] = x2 * c + x1 * s;
        __syncthreads();
        float a = buf[sub][h][2 * i], bb = buf[sub][h][2 * i + 1];
        uint32_t hi, lo;
        splitbf(a, bb, hi, lo);
        g_khp[t * 128 + h * 32 + i] = hi;
        g_klp[t * 128 + h * 32 + i] = lo;
    } else {
        int idx = (b - 2048) * 256 + threadIdx.x;
        float2 v = *(const float2*)&g_v[(size_t)idx * 2];
        uint32_t hi, lo;
        splitbf(v.x, v.y, hi, lo);
        g_vhp[idx] = hi;
        g_vlp[idx] = lo;
    }
}

// ---------------- cp.async tf32 GEMM (R10 proven: BK=16, 4-stage, ldsm A) ---
#define AS_ST 20
#define BS_ST 136
#define AS_STAGE (128 * AS_ST)
#define BS_STAGE (16 * BS_ST)
#define GEMM_SMEM ((4 * (AS_STAGE + BS_STAGE)) * 4)

template <int SILU, int ROUND, int TRANSC>
__device__ __forceinline__ void gemm_body(
    const float* __restrict__ A, const float* __restrict__ B,
    float* __restrict__ C, int N, int K, int rowBase, int colBase)
{
    extern __shared__ float smp[];
    float* As = smp;
    float* Bs = smp + 4 * AS_STAGE;

    int tid  = threadIdx.x;
    int lane = tid & 31;
    int warp = tid >> 5;
    int wm = (warp & 1) * 64;
    int wn = (warp >> 1) * 32;

    int ar  = tid >> 2;
    int ac  = (tid & 3) << 2;
    int bkr = tid >> 5;
    int bc  = (tid & 31) << 2;

    const float* Ag0 = A + (size_t)(rowBase + ar) * K + ac;
    const float* Ag1 = A + (size_t)(rowBase + 64 + ar) * K + ac;
    const float* Bg  = B + colBase + bc;

    uint32_t smem_b = (uint32_t)__cvta_generic_to_shared(smp);
    uint32_t loA = ((wm + (lane & 7) + ((lane >> 3) & 1) * 8) * AS_ST
                    + (lane >> 4) * 4) * 4;

    int nk = K >> 4;

#pragma unroll
    for (int s = 0; s < 3; s++) {
        if (s < nk) {
            float* as = As + s * AS_STAGE;
            float* bs = Bs + s * BS_STAGE;
            int k0 = s << 4;
            cp16(as + ar * AS_ST + ac,        Ag0 + k0);
            cp16(as + (ar + 64) * AS_ST + ac, Ag1 + k0);
            cp16(bs + bkr * BS_ST + bc,       Bg + (size_t)(k0 + bkr) * N);
            cp16(bs + (bkr + 8) * BS_ST + bc, Bg + (size_t)(k0 + 8 + bkr) * N);
        }
        asm volatile("cp.async.commit_group;");
    }

    float acc[4][4][4];
#pragma unroll
    for (int i = 0; i < 4; i++)
#pragma unroll
        for (int j = 0; j < 4; j++)
#pragma unroll
            for (int q = 0; q < 4; q++) acc[i][j][q] = 0.0f;

    for (int kt = 0; kt < nk; kt++) {
        asm volatile("cp.async.wait_group 2;");
        __syncthreads();

        int nx = kt + 3;
        if (nx < nk) {
            int bufn = nx & 3;
            float* as = As + bufn * AS_STAGE;
            float* bs = Bs + bufn * BS_STAGE;
            int k0 = nx << 4;
            cp16(as + ar * AS_ST + ac,        Ag0 + k0);
            cp16(as + (ar + 64) * AS_ST + ac, Ag1 + k0);
            cp16(bs + bkr * BS_ST + bc,       Bg + (size_t)(k0 + bkr) * N);
            cp16(bs + (bkr + 8) * BS_ST + bc, Bg + (size_t)(k0 + 8 + bkr) * N);
        }
        asm volatile("cp.async.commit_group;");

        uint32_t asb = smem_b + ((kt & 3) * AS_STAGE) * 4 + loA;
        const float* bs = Bs + (kt & 3) * BS_STAGE;
#pragma unroll
        for (int ks = 0; ks < 16; ks += 8) {
            uint32_t af[4][4], bf[4][2];
#pragma unroll
            for (int i = 0; i < 4; i++) {
                ldsm_x4(af[i][0], af[i][1], af[i][2], af[i][3],
                        asb + (i * 16 * AS_ST + ks) * 4);
            }
#pragma unroll
            for (int j = 0; j < 4; j++) {
                int kk = ks + (lane & 3);
                int n  = wn + j * 8 + (lane >> 2);
                bf[j][0] = __float_as_uint(bs[kk * BS_ST + n]);
                bf[j][1] = __float_as_uint(bs[(kk + 4) * BS_ST + n]);
            }
#pragma unroll
            for (int i = 0; i < 4; i++)
#pragma unroll
                for (int j = 0; j < 4; j++)
                    mma_tf32(acc[i][j], af[i], bf[j], acc[i][j]);
        }
    }

#pragma unroll
    for (int i = 0; i < 4; i++) {
        int r0 = rowBase + wm + i * 16 + (lane >> 2);
#pragma unroll
        for (int j = 0; j < 4; j++) {
            int c0 = colBase + wn + j * 8 + (lane & 3) * 2;
            float2 v0, v1;
            v0.x = acc[i][j][0]; v0.y = acc[i][j][1];
            v1.x = acc[i][j][2]; v1.y = acc[i][j][3];
            if (SILU) {
                v0.x = v0.x / (1.0f + expf(-v0.x));
                v0.y = v0.y / (1.0f + expf(-v0.y));
                v1.x = v1.x / (1.0f + expf(-v1.x));
                v1.y = v1.y / (1.0f + expf(-v1.y));
            }
            if (ROUND) {
                v0.x = roundtf(v0.x); v0.y = roundtf(v0.y);
                v1.x = roundtf(v1.x); v1.y = roundtf(v1.y);
            }
            if (TRANSC) {
                C[(size_t)c0 * T_SEQ + r0]           = v0.x;
                C[(size_t)(c0 + 1) * T_SEQ + r0]     = v0.y;
                C[(size_t)c0 * T_SEQ + r0 + 8]       = v1.x;
                C[(size_t)(c0 + 1) * T_SEQ + r0 + 8] = v1.y;
            } else {
                *(float2*)&C[(size_t)r0 * N + c0]       = v0;
                *(float2*)&C[(size_t)(r0 + 8) * N + c0] = v1;
            }
        }
    }
}

template <int SILU, int ROUND>
__global__ void __launch_bounds__(256, 2) tgemm2_kernel(
    const float* __restrict__ A, const float* __restrict__ B,
    float* __restrict__ C, int N, int K)
{
    gemm_body<SILU, ROUND, 0>(A, B, C, N, K, blockIdx.y * 128, blockIdx.x * 128);
}

__global__ void __launch_bounds__(256, 2) qkv_kernel(
    const float* __restrict__ Xt,
    const float* __restrict__ Wqt, const float* __restrict__ Wkt,
    const float* __restrict__ Wvt,
    float* __restrict__ q, float* __restrict__ k, float* __restrict__ v)
{
    int bx = blockIdx.x;
    if (bx < 8) {
        gemm_body<0, 0, 0>(Xt, Wqt, q, D_MODEL, D_MODEL,
                           blockIdx.y * 128, bx * 128);
    } else if (bx < 10) {
        gemm_body<0, 0, 0>(Xt, Wkt, k, NKV * HD, D_MODEL,
                           blockIdx.y * 128, (bx - 8) * 128);
    } else {
        gemm_body<0, 0, 1>(Xt, Wvt, v, NKV * HD, D_MODEL,
                           blockIdx.y * 128, (bx - 10) * 128);
    }
}

// ---------------- bf16 MMA flash attention (BM=128, BN=128) ----------------
// RoPE on Q fused into Q-staging (raw Q in, rope applied in smem).
#define KR_K 68
#define KR_V 132
#define KARR (128 * KR_K)           // 8704 u32
#define VARR (64 * KR_V)            // 8448 u32
#define STAGE_U (KARR + VARR)       // 17152 u32
#define ATT_SMEM (2 * STAGE_U * 4)  // 137216 bytes

__global__ void __launch_bounds__(256) attn_bf16_kernel(
    const float* __restrict__ qp,
    const uint32_t* __restrict__ khp, const uint32_t* __restrict__ klp,
    const uint32_t* __restrict__ vhp, const uint32_t* __restrict__ vlp,
    float* __restrict__ op)
{
    extern __shared__ uint32_t smu[];
    float* Qs = (float*)smu;

    int qb   = gridDim.x - 1 - blockIdx.x;
    int h    = blockIdx.y;
    int kvh  = h >> 2;
    int tid  = threadIdx.x;
    int lane = tid & 31;
    int warp = tid >> 5;
    int gid  = lane >> 2;
    int tig  = lane & 3;
    int tg2  = tig * 2;
    int fr   = warp * 16 + gid;

    // ---- stage raw Q tile ----
#pragma unroll
    for (int i = 0; i < 8; i++) {
        int e = tid + 256 * i;
        int r = e >> 4, c4 = (e & 15) << 2;
        *(float4*)&Qs[r * 64 + c4] =
            *(const float4*)&qp[(size_t)(qb * 128 + r) * D_MODEL + h * HD + c4];
    }
    __syncthreads();

    // ---- in-place RoPE ----
#pragma unroll
    for (int it = 0; it < 16; it++) {
        int p = tid + 256 * it;
        int r = p >> 5, i = p & 31;
        float c = g_cos[(qb * 128 + r) * 32 + i];
        float s = g_sin[(qb * 128 + r) * 32 + i];
        float x1 = Qs[r * 64 + i], x2 = Qs[r * 64 + i + 32];
        Qs[r * 64 + i]      = x1 * c - x2 * s;
        Qs[r * 64 + i + 32] = x2 * c + x1 * s;
    }
    __syncthreads();

    uint32_t qhi[4][4], qlo[4][4];
#pragma unroll
    for (int kt = 0; kt < 4; kt++) {
        float2 x0 = *(float2*)&Qs[fr * 64 + kt * 16 + tg2];
        float2 x1 = *(float2*)&Qs[(fr + 8) * 64 + kt * 16 + tg2];
        float2 x2 = *(float2*)&Qs[fr * 64 + kt * 16 + tg2 + 8];
        float2 x3 = *(float2*)&Qs[(fr + 8) * 64 + kt * 16 + tg2 + 8];
        splitbf(x0.x * 0.125f, x0.y * 0.125f, qhi[kt][0], qlo[kt][0]);
        splitbf(x1.x * 0.125f, x1.y * 0.125f, qhi[kt][1], qlo[kt][1]);
        splitbf(x2.x * 0.125f, x2.y * 0.125f, qhi[kt][2], qlo[kt][2]);
        splitbf(x3.x * 0.125f, x3.y * 0.125f, qhi[kt][3], qlo[kt][3]);
    }
    __syncthreads();   // Q reads done before cp.async overwrites stage 0

    uint32_t smem_b = (uint32_t)__cvta_generic_to_shared(smu);
    int loK = (lane & 7) * KR_K + ((lane >> 3) & 1) * 4 + (lane >> 4) * 32;
    int loV = (lane & 7) * KR_V + ((lane >> 3) & 1) * 4 + (lane >> 4) * 64;

    int rK = tid >> 1, hK = (tid & 1) * 16;
    int rV = tid >> 2, qV = (tid & 3) * 16;
    const uint32_t* khB = khp + kvh * 32;
    const uint32_t* klB = klp + kvh * 32;
    const uint32_t* vhB = vhp + (size_t)(kvh * HD + rV) * (T_SEQ / 2);
    const uint32_t* vlB = vlp + (size_t)(kvh * HD + rV) * (T_SEQ / 2);

    int kbmax = qb;

    {
        uint32_t* Ks = smu;
        uint32_t* Vs = smu + KARR;
#pragma unroll
        for (int j = 0; j < 4; j++) {
            int c = hK + j * 4;
            cp16u(Ks + rK * KR_K + c,      khB + (size_t)rK * 128 + c);
            cp16u(Ks + rK * KR_K + 32 + c, klB + (size_t)rK * 128 + c);
        }
#pragma unroll
        for (int j = 0; j < 4; j++) {
            int c = qV + j * 4;
            cp16u(Vs + rV * KR_V + c,      vhB + c);
            cp16u(Vs + rV * KR_V + 64 + c, vlB + c);
        }
        asm volatile("cp.async.commit_group;");
    }

    float oacc[8][4];
#pragma unroll
    for (int nt = 0; nt < 8; nt++)
#pragma unroll
        for (int j = 0; j < 4; j++) oacc[nt][j] = 0.0f;
    float m0 = -1e30f, m1 = -1e30f, l0 = 0.0f, l1 = 0.0f;

    for (int kb = 0; kb <= kbmax; kb++) {
        asm volatile("cp.async.wait_group 0;");
        __syncthreads();

        if (kb < kbmax) {
            uint32_t* st = smu + ((kb + 1) & 1) * STAGE_U;
            uint32_t* Ks = st;
            uint32_t* Vs = st + KARR;
            int tk = (kb + 1) * 128;
            int tv = (kb + 1) * 64;
#pragma unroll
            for (int j = 0; j < 4; j++) {
                int c = hK + j * 4;
                cp16u(Ks + rK * KR_K + c,      khB + (size_t)(tk + rK) * 128 + c);
                cp16u(Ks + rK * KR_K + 32 + c, klB + (size_t)(tk + rK) * 128 + c);
            }
#pragma unroll
            for (int j = 0; j < 4; j++) {
                int c = qV + j * 4;
                cp16u(Vs + rV * KR_V + c,      vhB + tv + c);
                cp16u(Vs + rV * KR_V + 64 + c, vlB + tv + c);
            }
        }
        asm volatile("cp.async.commit_group;");

        uint32_t stK = smem_b + 4 * ((kb & 1) * STAGE_U + loK);
        uint32_t stV = smem_b + 4 * ((kb & 1) * STAGE_U + KARR + loV);

        float sacc[16][4];
#pragma unroll
        for (int nt = 0; nt < 16; nt++)
#pragma unroll
            for (int j = 0; j < 4; j++) sacc[nt][j] = 0.0f;

#pragma unroll
        for (int nt = 0; nt < 16; nt++) {
            uint32_t rowa = stK + nt * (8 * KR_K * 4);
#pragma unroll
            for (int ks = 0; ks < 4; ks++) {
                uint32_t bh0, bh1, bl0, bl1;
                ldsm_x4(bh0, bh1, bl0, bl1, rowa + ks * 32);
                uint32_t bh[2] = {bh0, bh1}, bl[2] = {bl0, bl1};
                mma_bf16(sacc[nt], qhi[ks], bh, sacc[nt]);
                mma_bf16(sacc[nt], qlo[ks], bh, sacc[nt]);
                mma_bf16(sacc[nt], qhi[ks], bl, sacc[nt]);
            }
        }

        if (kb == qb) {
            int grow0 = qb * 128 + fr;
            int grow1 = grow0 + 8;
#pragma unroll
            for (int nt = 0; nt < 16; nt++) {
                int gc = kb * 128 + nt * 8 + tg2;
                if (gc     > grow0) sacc[nt][0] = -1e30f;
                if (gc + 1 > grow0) sacc[nt][1] = -1e30f;
                if (gc     > grow1) sacc[nt][2] = -1e30f;
                if (gc + 1 > grow1) sacc[nt][3] = -1e30f;
            }
        }

        float mx0 = -1e30f, mx1 = -1e30f;
#pragma unroll
        for (int nt = 0; nt < 16; nt++) {
            mx0 = fmaxf(mx0, fmaxf(sacc[nt][0], sacc[nt][1]));
            mx1 = fmaxf(mx1, fmaxf(sacc[nt][2], sacc[nt][3]));
        }
        mx0 = fmaxf(mx0, __shfl_xor_sync(0xffffffffu, mx0, 1));
        mx0 = fmaxf(mx0, __shfl_xor_sync(0xffffffffu, mx0, 2));
        mx1 = fmaxf(mx1, __shfl_xor_sync(0xffffffffu, mx1, 1));
        mx1 = fmaxf(mx1, __shfl_xor_sync(0xffffffffu, mx1, 2));

        float mn0 = fmaxf(m0, mx0), mn1 = fmaxf(m1, mx1);
        float c0 = __expf(m0 - mn0), c1 = __expf(m1 - mn1);
        float rs0 = 0.0f, rs1 = 0.0f;
#pragma unroll
        for (int nt = 0; nt < 16; nt++) {
            float p0 = __expf(sacc[nt][0] - mn0);
            float p1 = __expf(sacc[nt][1] - mn0);
            float p2 = __expf(sacc[nt][2] - mn1);
            float p3 = __expf(sacc[nt][3] - mn1);
            sacc[nt][0] = p0; sacc[nt][1] = p1;
            sacc[nt][2] = p2; sacc[nt][3] = p3;
            rs0 += p0 + p1;
            rs1 += p2 + p3;
        }
        rs0 += __shfl_xor_sync(0xffffffffu, rs0, 1);
        rs0 += __shfl_xor_sync(0xffffffffu, rs0, 2);
        rs1 += __shfl_xor_sync(0xffffffffu, rs1, 1);
        rs1 += __shfl_xor_sync(0xffffffffu, rs1, 2);
        l0 = l0 * c0 + rs0;  m0 = mn0;
        l1 = l1 * c1 + rs1;  m1 = mn1;
#pragma unroll
        for (int nt = 0; nt < 8; nt++) {
            oacc[nt][0] *= c0; oacc[nt][1] *= c0;
            oacc[nt][2] *= c1; oacc[nt][3] *= c1;
        }

#pragma unroll
        for (int kt = 0; kt < 8; kt++) {
            uint32_t ahi[4], alo[4];
            splitbf(sacc[2*kt][0],     sacc[2*kt][1],     ahi[0], alo[0]);
            splitbf(sacc[2*kt][2],     sacc[2*kt][3],     ahi[1], alo[1]);
            splitbf(sacc[2*kt + 1][0], sacc[2*kt + 1][1], ahi[2], alo[2]);
            splitbf(sacc[2*kt + 1][2], sacc[2*kt + 1][3], ahi[3], alo[3]);
#pragma unroll
            for (int nt = 0; nt < 8; nt++) {
                uint32_t bh0, bh1, bl0, bl1;
                ldsm_x4(bh0, bh1, bl0, bl1,
                        stV + nt * (8 * KR_V * 4) + kt * 32);
                uint32_t bh[2] = {bh0, bh1}, bl[2] = {bl0, bl1};
                mma_bf16(oacc[nt], ahi, bh, oacc[nt]);
                mma_bf16(oacc[nt], alo, bh, oacc[nt]);
                mma_bf16(oacc[nt], ahi, bl, oacc[nt]);
            }
        }
    }

    float inv0 = 1.0f / l0, inv1 = 1.0f / l1;
#pragma unroll
    for (int nt = 0; nt < 8; nt++) {
        int col = h * HD + nt * 8 + tg2;
        float2 w0, w1;
        w0.x = roundtf(oacc[nt][0] * inv0); w0.y = roundtf(oacc[nt][1] * inv0);
        w1.x = roundtf(oacc[nt][2] * inv1); w1.y = roundtf(oacc[nt][3] * inv1);
        *(float2*)&op[(size_t)(qb * 128 + fr) * D_MODEL + col]     = w0;
        *(float2*)&op[(size_t)(qb * 128 + fr + 8) * D_MODEL + col] = w1;
    }
}

// ---------------- launch ---------------------------------------------------
extern "C" void kernel_launch(void* const* d_in, const int* in_sizes, int n_in,
                              void* d_out, int out_size)
{
    const float* X  = (const float*)d_in[0];
    const float* Wq = (const float*)d_in[1];
    const float* Wk = (const float*)d_in[2];
    const float* Wv = (const float*)d_in[3];
    const float* W1 = (const float*)d_in[4];
    const float* W2 = (const float*)d_in[5];
    float* out = (float*)d_out;

    float *gq, *gk, *gv, *ga, *gh;
    float *gxt, *gwqt, *gwkt, *gwvt, *gw1t, *gw2t;
    uint32_t *gkh, *gkl, *gvh, *gvl;
    cudaGetSymbolAddress((void**)&gq, g_q);
    cudaGetSymbolAddress((void**)&gk, g_k);
    cudaGetSymbolAddress((void**)&gv, g_v);
    cudaGetSymbolAddress((void**)&ga, g_attn);
    cudaGetSymbolAddress((void**)&gh, g_h1);
    cudaGetSymbolAddress((void**)&gxt, g_xt);
    cudaGetSymbolAddress((void**)&gwqt, g_wqt);
    cudaGetSymbolAddress((void**)&gwkt, g_wkt);
    cudaGetSymbolAddress((void**)&gwvt, g_wvt);
    cudaGetSymbolAddress((void**)&gw1t, g_w1t);
    cudaGetSymbolAddress((void**)&gw2t, g_w2t);
    cudaGetSymbolAddress((void**)&gkh, g_khp);
    cudaGetSymbolAddress((void**)&gkl, g_klp);
    cudaGetSymbolAddress((void**)&gvh, g_vhp);
    cudaGetSymbolAddress((void**)&gvl, g_vlp);

    cudaFuncSetAttribute(attn_bf16_kernel,
                         cudaFuncAttributeMaxDynamicSharedMemorySize, ATT_SMEM);
    cudaFuncSetAttribute(qkv_kernel,
                         cudaFuncAttributeMaxDynamicSharedMemorySize, GEMM_SMEM);
    cudaFuncSetAttribute(tgemm2_kernel<1, 1>,
                         cudaFuncAttributeMaxDynamicSharedMemorySize, GEMM_SMEM);
    cudaFuncSetAttribute(tgemm2_kernel<0, 0>,
                         cudaFuncAttributeMaxDynamicSharedMemorySize, GEMM_SMEM);

    // merged pre-round + rope table (3456 round chunks + 512 table blocks)
    round_all_kernel<<<3968, 256>>>(X, Wq, Wk, Wv, W1, W2);
    qkv_kernel<<<dim3(12, T_SEQ / 128), 256, GEMM_SMEM>>>(
        gxt, gwqt, gwkt, gwvt, gq, gk, gv);
    prep_kv_kernel<<<4096, 256>>>();
    attn_bf16_kernel<<<dim3(T_SEQ / 128, NH), 256, ATT_SMEM>>>(
        gq, gkh, gkl, gvh, gvl, ga);
    tgemm2_kernel<1, 1><<<dim3(D_FF / 128, T_SEQ / 128), 256, GEMM_SMEM>>>(
        ga, gw1t, gh, D_FF, D_MODEL);
    tgemm2_kernel<0, 0><<<dim3(D_MODEL / 128, T_SEQ / 128), 256, GEMM_SMEM>>>(
        gh, gw2t, out, D_MODEL, D_FF);
}

// round 16
// speedup vs baseline: 1.3616x; 1.0061x over previous
#include <cuda_runtime.h>
#include <cuda_bf16.h>
#include <math.h>
#include <stdint.h>

// Problem constants
#define T_SEQ  4096
#define D_MODEL 1024
#define NH     16
#define NKV    4
#define HD     64
#define D_FF   4096

// ---------------- scratch (device globals; no allocation allowed) ----------
__device__ float g_q[T_SEQ * D_MODEL];          // raw (pre-rope) Q
__device__ float g_k[T_SEQ * NKV * HD];         // [token][256] (pre-rope)
__device__ float g_v[NKV * HD * T_SEQ];         // TRANSPOSED [256][4096]
__device__ float g_attn[T_SEQ * D_MODEL];       // tf32-rounded
__device__ float g_h1[(size_t)T_SEQ * D_FF];    // tf32-rounded
__device__ float g_cos[T_SEQ * 32];
__device__ float g_sin[T_SEQ * 32];
__device__ float g_xt[T_SEQ * D_MODEL];
__device__ float g_wqt[D_MODEL * D_MODEL];
__device__ float g_wkt[D_MODEL * NKV * HD];
__device__ float g_wvt[D_MODEL * NKV * HD];
__device__ float g_w1t[D_MODEL * D_FF];
__device__ float g_w2t[D_FF * D_MODEL];
__device__ uint32_t g_khp[T_SEQ * 128];         // [token][kvh*32 + d2] bf16x2 hi
__device__ uint32_t g_klp[T_SEQ * 128];
__device__ uint32_t g_vhp[NKV * HD * (T_SEQ / 2)];  // [dim][token-pair]
__device__ uint32_t g_vlp[NKV * HD * (T_SEQ / 2)];

// ---------------- helpers ---------------------------------------------------
__device__ __forceinline__ uint32_t f2tf32(float x) {
    uint32_t r;
    asm("cvt.rna.tf32.f32 %0, %1;" : "=r"(r) : "f"(x));
    return r;
}
__device__ __forceinline__ float roundtf(float x) {
    return __uint_as_float(f2tf32(x));
}

__device__ __forceinline__ void mma_tf32(float* d, const uint32_t* a,
                                         const uint32_t* b, const float* c) {
    asm volatile(
        "mma.sync.aligned.m16n8k8.row.col.f32.tf32.tf32.f32 "
        "{%0,%1,%2,%3}, {%4,%5,%6,%7}, {%8,%9}, {%10,%11,%12,%13};"
        : "=f"(d[0]), "=f"(d[1]), "=f"(d[2]), "=f"(d[3])
        : "r"(a[0]), "r"(a[1]), "r"(a[2]), "r"(a[3]),
          "r"(b[0]), "r"(b[1]),
          "f"(c[0]), "f"(c[1]), "f"(c[2]), "f"(c[3]));
}

__device__ __forceinline__ void mma_bf16(float* d, const uint32_t* a,
                                         const uint32_t* b, const float* c) {
    asm volatile(
        "mma.sync.aligned.m16n8k16.row.col.f32.bf16.bf16.f32 "
        "{%0,%1,%2,%3}, {%4,%5,%6,%7}, {%8,%9}, {%10,%11,%12,%13};"
        : "=f"(d[0]), "=f"(d[1]), "=f"(d[2]), "=f"(d[3])
        : "r"(a[0]), "r"(a[1]), "r"(a[2]), "r"(a[3]),
          "r"(b[0]), "r"(b[1]),
          "f"(c[0]), "f"(c[1]), "f"(c[2]), "f"(c[3]));
}

__device__ __forceinline__ void ldsm_x4(uint32_t& r0, uint32_t& r1,
                                        uint32_t& r2, uint32_t& r3,
                                        uint32_t saddr) {
    asm volatile(
        "ldmatrix.sync.aligned.m8n8.x4.shared.b16 {%0,%1,%2,%3}, [%4];"
        : "=r"(r0), "=r"(r1), "=r"(r2), "=r"(r3) : "r"(saddr));
}

__device__ __forceinline__ uint32_t packbf(float x, float y) {
    __nv_bfloat162 t = __floats2bfloat162_rn(x, y);
    return *(uint32_t*)&t;
}
__device__ __forceinline__ void splitbf(float x, float y,
                                        uint32_t& hi, uint32_t& lo) {
    __nv_bfloat16 hx = __float2bfloat16_rn(x);
    __nv_bfloat16 hy = __float2bfloat16_rn(y);
    hi = packbf(__bfloat162float(hx), __bfloat162float(hy));
    lo = packbf(x - __bfloat162float(hx), y - __bfloat162float(hy));
}

__device__ __forceinline__ void cp16(float* smem_dst, const float* g) {
    uint32_t a = (uint32_t)__cvta_generic_to_shared(smem_dst);
    asm volatile("cp.async.ca.shared.global [%0], [%1], 16;" :: "r"(a), "l"(g));
}
__device__ __forceinline__ void cp16u(uint32_t* smem_dst, const uint32_t* g) {
    uint32_t a = (uint32_t)__cvta_generic_to_shared(smem_dst);
    asm volatile("cp.async.ca.shared.global [%0], [%1], 16;" :: "r"(a), "l"(g));
}

// ---------------- merged pre-round + rope-table pass ------------------------
// Chunks of 1024 float4 (4 per thread, stride 256):
//   X 1024 | Wq 256 | Wk 64 | Wv 64 | W1 1024 | W2 1024 = 3456 chunks
// Blocks [3456, 3968): rope cos/sin table (131072 angles).
__global__ void round_all_kernel(
    const float* __restrict__ X,  const float* __restrict__ Wq,
    const float* __restrict__ Wk, const float* __restrict__ Wv,
    const float* __restrict__ W1, const float* __restrict__ W2)
{
    int b = blockIdx.x;
    if (b >= 3456) {
        int idx = (b - 3456) * 256 + threadIdx.x;   // 0..131071 == t*32 + i
        int i = idx & 31;
        float inv = 1.0f / powf(10000.0f, (float)(2 * i) / 64.0f);
        float ang = (float)(idx >> 5) * inv;
        g_cos[idx] = cosf(ang);
        g_sin[idx] = sinf(ang);
        return;
    }
    const float* src;
    float* dst;
    int base;
    if      (b < 1024) { src = X;  dst = g_xt;  base = 0;    }
    else if (b < 1280) { src = Wq; dst = g_wqt; base = 1024; }
    else if (b < 1344) { src = Wk; dst = g_wkt; base = 1280; }
    else if (b < 1408) { src = Wv; dst = g_wvt; base = 1344; }
    else if (b < 2432) { src = W1; dst = g_w1t; base = 1408; }
    else               { src = W2; dst = g_w2t; base = 2432; }
    size_t off = (size_t)(b - base) * 1024 + threadIdx.x;
#pragma unroll
    for (int j = 0; j < 4; j++) {
        float4 v = ((const float4*)src)[off + j * 256];
        v.x = roundtf(v.x); v.y = roundtf(v.y);
        v.z = roundtf(v.z); v.w = roundtf(v.w);
        ((float4*)dst)[off + j * 256] = v;
    }
}

// ---------------- fused KV prep ---------------------------------------------
__global__ void prep_kv_kernel() {
    int b = blockIdx.x;
    if (b < 2048) {
        __shared__ float buf[2][NKV][64];
        int sub = threadIdx.x >> 7;
        int wt  = threadIdx.x & 127;
        int t = b * 2 + sub;
        int h = wt >> 5;
        int i = wt & 31;
        float c = g_cos[t * 32 + i];
        float s = g_sin[t * 32 + i];
        const float* p = g_k + (size_t)t * (NKV * HD) + h * HD;
        float x1 = p[i], x2 = p[i + 32];
        buf[sub][h][i]      = x1 * c - x2 * s;
        buf[sub][h][i + 32] = x2 * c + x1 * s;
        __syncthreads();
        float a = buf[sub][h][2 * i], bb = buf[sub][h][2 * i + 1];
        uint32_t hi, lo;
        splitbf(a, bb, hi, lo);
        g_khp[t * 128 + h * 32 + i] = hi;
        g_klp[t * 128 + h * 32 + i] = lo;
    } else {
        int idx = (b - 2048) * 256 + threadIdx.x;
        float2 v = *(const float2*)&g_v[(size_t)idx * 2];
        uint32_t hi, lo;
        splitbf(v.x, v.y, hi, lo);
        g_vhp[idx] = hi;
        g_vlp[idx] = lo;
    }
}

// ---------------- cp.async tf32 GEMM (R10 proven: BK=16, 4-stage, ldsm A) ---
#define AS_ST 20
#define BS_ST 136
#define AS_STAGE (128 * AS_ST)
#define BS_STAGE (16 * BS_ST)
#define GEMM_SMEM ((4 * (AS_STAGE + BS_STAGE)) * 4)

template <int SILU, int ROUND, int TRANSC>
__device__ __forceinline__ void gemm_body(
    const float* __restrict__ A, const float* __restrict__ B,
    float* __restrict__ C, int N, int K, int rowBase, int colBase)
{
    extern __shared__ float smp[];
    float* As = smp;
    float* Bs = smp + 4 * AS_STAGE;

    int tid  = threadIdx.x;
    int lane = tid & 31;
    int warp = tid >> 5;
    int wm = (warp & 1) * 64;
    int wn = (warp >> 1) * 32;

    int ar  = tid >> 2;
    int ac  = (tid & 3) << 2;
    int bkr = tid >> 5;
    int bc  = (tid & 31) << 2;

    const float* Ag0 = A + (size_t)(rowBase + ar) * K + ac;
    const float* Ag1 = A + (size_t)(rowBase + 64 + ar) * K + ac;
    const float* Bg  = B + colBase + bc;

    uint32_t smem_b = (uint32_t)__cvta_generic_to_shared(smp);
    uint32_t loA = ((wm + (lane & 7) + ((lane >> 3) & 1) * 8) * AS_ST
                    + (lane >> 4) * 4) * 4;

    int nk = K >> 4;

#pragma unroll
    for (int s = 0; s < 3; s++) {
        if (s < nk) {
            float* as = As + s * AS_STAGE;
            float* bs = Bs + s * BS_STAGE;
            int k0 = s << 4;
            cp16(as + ar * AS_ST + ac,        Ag0 + k0);
            cp16(as + (ar + 64) * AS_ST + ac, Ag1 + k0);
            cp16(bs + bkr * BS_ST + bc,       Bg + (size_t)(k0 + bkr) * N);
            cp16(bs + (bkr + 8) * BS_ST + bc, Bg + (size_t)(k0 + 8 + bkr) * N);
        }
        asm volatile("cp.async.commit_group;");
    }

    float acc[4][4][4];
#pragma unroll
    for (int i = 0; i < 4; i++)
#pragma unroll
        for (int j = 0; j < 4; j++)
#pragma unroll
            for (int q = 0; q < 4; q++) acc[i][j][q] = 0.0f;

    for (int kt = 0; kt < nk; kt++) {
        asm volatile("cp.async.wait_group 2;");
        __syncthreads();

        int nx = kt + 3;
        if (nx < nk) {
            int bufn = nx & 3;
            float* as = As + bufn * AS_STAGE;
            float* bs = Bs + bufn * BS_STAGE;
            int k0 = nx << 4;
            cp16(as + ar * AS_ST + ac,        Ag0 + k0);
            cp16(as + (ar + 64) * AS_ST + ac, Ag1 + k0);
            cp16(bs + bkr * BS_ST + bc,       Bg + (size_t)(k0 + bkr) * N);
            cp16(bs + (bkr + 8) * BS_ST + bc, Bg + (size_t)(k0 + 8 + bkr) * N);
        }
        asm volatile("cp.async.commit_group;");

        uint32_t asb = smem_b + ((kt & 3) * AS_STAGE) * 4 + loA;
        const float* bs = Bs + (kt & 3) * BS_STAGE;
#pragma unroll
        for (int ks = 0; ks < 16; ks += 8) {
            uint32_t af[4][4], bf[4][2];
#pragma unroll
            for (int i = 0; i < 4; i++) {
                ldsm_x4(af[i][0], af[i][1], af[i][2], af[i][3],
                        asb + (i * 16 * AS_ST + ks) * 4);
            }
#pragma unroll
            for (int j = 0; j < 4; j++) {
                int kk = ks + (lane & 3);
                int n  = wn + j * 8 + (lane >> 2);
                bf[j][0] = __float_as_uint(bs[kk * BS_ST + n]);
                bf[j][1] = __float_as_uint(bs[(kk + 4) * BS_ST + n]);
            }
#pragma unroll
            for (int i = 0; i < 4; i++)
#pragma unroll
                for (int j = 0; j < 4; j++)
                    mma_tf32(acc[i][j], af[i], bf[j], acc[i][j]);
        }
    }

#pragma unroll
    for (int i = 0; i < 4; i++) {
        int r0 = rowBase + wm + i * 16 + (lane >> 2);
#pragma unroll
        for (int j = 0; j < 4; j++) {
            int c0 = colBase + wn + j * 8 + (lane & 3) * 2;
            float2 v0, v1;
            v0.x = acc[i][j][0]; v0.y = acc[i][j][1];
            v1.x = acc[i][j][2]; v1.y = acc[i][j][3];
            if (SILU) {
                v0.x = v0.x / (1.0f + expf(-v0.x));
                v0.y = v0.y / (1.0f + expf(-v0.y));
                v1.x = v1.x / (1.0f + expf(-v1.x));
                v1.y = v1.y / (1.0f + expf(-v1.y));
            }
            if (ROUND) {
                v0.x = roundtf(v0.x); v0.y = roundtf(v0.y);
                v1.x = roundtf(v1.x); v1.y = roundtf(v1.y);
            }
            if (TRANSC) {
                C[(size_t)c0 * T_SEQ + r0]           = v0.x;
                C[(size_t)(c0 + 1) * T_SEQ + r0]     = v0.y;
                C[(size_t)c0 * T_SEQ + r0 + 8]       = v1.x;
                C[(size_t)(c0 + 1) * T_SEQ + r0 + 8] = v1.y;
            } else {
                *(float2*)&C[(size_t)r0 * N + c0]       = v0;
                *(float2*)&C[(size_t)(r0 + 8) * N + c0] = v1;
            }
        }
    }
}

template <int SILU, int ROUND>
__global__ void __launch_bounds__(256, 2) tgemm2_kernel(
    const float* __restrict__ A, const float* __restrict__ B,
    float* __restrict__ C, int N, int K)
{
    gemm_body<SILU, ROUND, 0>(A, B, C, N, K, blockIdx.y * 128, blockIdx.x * 128);
}

__global__ void __launch_bounds__(256, 2) qkv_kernel(
    const float* __restrict__ Xt,
    const float* __restrict__ Wqt, const float* __restrict__ Wkt,
    const float* __restrict__ Wvt,
    float* __restrict__ q, float* __restrict__ k, float* __restrict__ v)
{
    int bx = blockIdx.x;
    if (bx < 8) {
        gemm_body<0, 0, 0>(Xt, Wqt, q, D_MODEL, D_MODEL,
                           blockIdx.y * 128, bx * 128);
    } else if (bx < 10) {
        gemm_body<0, 0, 0>(Xt, Wkt, k, NKV * HD, D_MODEL,
                           blockIdx.y * 128, (bx - 8) * 128);
    } else {
        gemm_body<0, 0, 1>(Xt, Wvt, v, NKV * HD, D_MODEL,
                           blockIdx.y * 128, (bx - 10) * 128);
    }
}

// ---------------- bf16 MMA flash attention (BM=128, BN=128) ----------------
// RoPE on Q fused into Q-staging. S-loop interchanged (ks outer, nt inner)
// so consecutive mma target independent accumulators.
#define KR_K 68
#define KR_V 132
#define KARR (128 * KR_K)           // 8704 u32
#define VARR (64 * KR_V)            // 8448 u32
#define STAGE_U (KARR + VARR)       // 17152 u32
#define ATT_SMEM (2 * STAGE_U * 4)  // 137216 bytes

__global__ void __launch_bounds__(256) attn_bf16_kernel(
    const float* __restrict__ qp,
    const uint32_t* __restrict__ khp, const uint32_t* __restrict__ klp,
    const uint32_t* __restrict__ vhp, const uint32_t* __restrict__ vlp,
    float* __restrict__ op)
{
    extern __shared__ uint32_t smu[];
    float* Qs = (float*)smu;

    int qb   = gridDim.x - 1 - blockIdx.x;
    int h    = blockIdx.y;
    int kvh  = h >> 2;
    int tid  = threadIdx.x;
    int lane = tid & 31;
    int warp = tid >> 5;
    int gid  = lane >> 2;
    int tig  = lane & 3;
    int tg2  = tig * 2;
    int fr   = warp * 16 + gid;

    // ---- stage raw Q tile ----
#pragma unroll
    for (int i = 0; i < 8; i++) {
        int e = tid + 256 * i;
        int r = e >> 4, c4 = (e & 15) << 2;
        *(float4*)&Qs[r * 64 + c4] =
            *(const float4*)&qp[(size_t)(qb * 128 + r) * D_MODEL + h * HD + c4];
    }
    __syncthreads();

    // ---- in-place RoPE ----
#pragma unroll
    for (int it = 0; it < 16; it++) {
        int p = tid + 256 * it;
        int r = p >> 5, i = p & 31;
        float c = g_cos[(qb * 128 + r) * 32 + i];
        float s = g_sin[(qb * 128 + r) * 32 + i];
        float x1 = Qs[r * 64 + i], x2 = Qs[r * 64 + i + 32];
        Qs[r * 64 + i]      = x1 * c - x2 * s;
        Qs[r * 64 + i + 32] = x2 * c + x1 * s;
    }
    __syncthreads();

    uint32_t qhi[4][4], qlo[4][4];
#pragma unroll
    for (int kt = 0; kt < 4; kt++) {
        float2 x0 = *(float2*)&Qs[fr * 64 + kt * 16 + tg2];
        float2 x1 = *(float2*)&Qs[(fr + 8) * 64 + kt * 16 + tg2];
        float2 x2 = *(float2*)&Qs[fr * 64 + kt * 16 + tg2 + 8];
        float2 x3 = *(float2*)&Qs[(fr + 8) * 64 + kt * 16 + tg2 + 8];
        splitbf(x0.x * 0.125f, x0.y * 0.125f, qhi[kt][0], qlo[kt][0]);
        splitbf(x1.x * 0.125f, x1.y * 0.125f, qhi[kt][1], qlo[kt][1]);
        splitbf(x2.x * 0.125f, x2.y * 0.125f, qhi[kt][2], qlo[kt][2]);
        splitbf(x3.x * 0.125f, x3.y * 0.125f, qhi[kt][3], qlo[kt][3]);
    }
    __syncthreads();   // Q reads done before cp.async overwrites stage 0

    uint32_t smem_b = (uint32_t)__cvta_generic_to_shared(smu);
    int loK = (lane & 7) * KR_K + ((lane >> 3) & 1) * 4 + (lane >> 4) * 32;
    int loV = (lane & 7) * KR_V + ((lane >> 3) & 1) * 4 + (lane >> 4) * 64;

    int rK = tid >> 1, hK = (tid & 1) * 16;
    int rV = tid >> 2, qV = (tid & 3) * 16;
    const uint32_t* khB = khp + kvh * 32;
    const uint32_t* klB = klp + kvh * 32;
    const uint32_t* vhB = vhp + (size_t)(kvh * HD + rV) * (T_SEQ / 2);
    const uint32_t* vlB = vlp + (size_t)(kvh * HD + rV) * (T_SEQ / 2);

    int kbmax = qb;

    {
        uint32_t* Ks = smu;
        uint32_t* Vs = smu + KARR;
#pragma unroll
        for (int j = 0; j < 4; j++) {
            int c = hK + j * 4;
            cp16u(Ks + rK * KR_K + c,      khB + (size_t)rK * 128 + c);
            cp16u(Ks + rK * KR_K + 32 + c, klB + (size_t)rK * 128 + c);
        }
#pragma unroll
        for (int j = 0; j < 4; j++) {
            int c = qV + j * 4;
            cp16u(Vs + rV * KR_V + c,      vhB + c);
            cp16u(Vs + rV * KR_V + 64 + c, vlB + c);
        }
        asm volatile("cp.async.commit_group;");
    }

    float oacc[8][4];
#pragma unroll
    for (int nt = 0; nt < 8; nt++)
#pragma unroll
        for (int j = 0; j < 4; j++) oacc[nt][j] = 0.0f;
    float m0 = -1e30f, m1 = -1e30f, l0 = 0.0f, l1 = 0.0f;

    for (int kb = 0; kb <= kbmax; kb++) {
        asm volatile("cp.async.wait_group 0;");
        __syncthreads();

        if (kb < kbmax) {
            uint32_t* st = smu + ((kb + 1) & 1) * STAGE_U;
            uint32_t* Ks = st;
            uint32_t* Vs = st + KARR;
            int tk = (kb + 1) * 128;
            int tv = (kb + 1) * 64;
#pragma unroll
            for (int j = 0; j < 4; j++) {
                int c = hK + j * 4;
                cp16u(Ks + rK * KR_K + c,      khB + (size_t)(tk + rK) * 128 + c);
                cp16u(Ks + rK * KR_K + 32 + c, klB + (size_t)(tk + rK) * 128 + c);
            }
#pragma unroll
            for (int j = 0; j < 4; j++) {
                int c = qV + j * 4;
                cp16u(Vs + rV * KR_V + c,      vhB + tv + c);
                cp16u(Vs + rV * KR_V + 64 + c, vlB + tv + c);
            }
        }
        asm volatile("cp.async.commit_group;");

        uint32_t stK = smem_b + 4 * ((kb & 1) * STAGE_U + loK);
        uint32_t stV = smem_b + 4 * ((kb & 1) * STAGE_U + KARR + loV);

        // ---- S = (Q/8) @ K^T : ks outer, nt inner (independent acc chains) --
        float sacc[16][4];
#pragma unroll
        for (int nt = 0; nt < 16; nt++)
#pragma unroll
            for (int j = 0; j < 4; j++) sacc[nt][j] = 0.0f;

#pragma unroll
        for (int ks = 0; ks < 4; ks++) {
#pragma unroll
            for (int nt = 0; nt < 16; nt++) {
                uint32_t bh0, bh1, bl0, bl1;
                ldsm_x4(bh0, bh1, bl0, bl1,
                        stK + nt * (8 * KR_K * 4) + ks * 32);
                uint32_t bh[2] = {bh0, bh1}, bl[2] = {bl0, bl1};
                mma_bf16(sacc[nt], qhi[ks], bh, sacc[nt]);
                mma_bf16(sacc[nt], qlo[ks], bh, sacc[nt]);
                mma_bf16(sacc[nt], qhi[ks], bl, sacc[nt]);
            }
        }

        if (kb == qb) {
            int grow0 = qb * 128 + fr;
            int grow1 = grow0 + 8;
#pragma unroll
            for (int nt = 0; nt < 16; nt++) {
                int gc = kb * 128 + nt * 8 + tg2;
                if (gc     > grow0) sacc[nt][0] = -1e30f;
                if (gc + 1 > grow0) sacc[nt][1] = -1e30f;
                if (gc     > grow1) sacc[nt][2] = -1e30f;
                if (gc + 1 > grow1) sacc[nt][3] = -1e30f;
            }
        }

        float mx0 = -1e30f, mx1 = -1e30f;
#pragma unroll
        for (int nt = 0; nt < 16; nt++) {
            mx0 = fmaxf(mx0, fmaxf(sacc[nt][0], sacc[nt][1]));
            mx1 = fmaxf(mx1, fmaxf(sacc[nt][2], sacc[nt][3]));
        }
        mx0 = fmaxf(mx0, __shfl_xor_sync(0xffffffffu, mx0, 1));
        mx0 = fmaxf(mx0, __shfl_xor_sync(0xffffffffu, mx0, 2));
        mx1 = fmaxf(mx1, __shfl_xor_sync(0xffffffffu, mx1, 1));
        mx1 = fmaxf(mx1, __shfl_xor_sync(0xffffffffu, mx1, 2));

        float mn0 = fmaxf(m0, mx0), mn1 = fmaxf(m1, mx1);
        float c0 = __expf(m0 - mn0), c1 = __expf(m1 - mn1);
        float rs0 = 0.0f, rs1 = 0.0f;
#pragma unroll
        for (int nt = 0; nt < 16; nt++) {
            float p0 = __expf(sacc[nt][0] - mn0);
            float p1 = __expf(sacc[nt][1] - mn0);
            float p2 = __expf(sacc[nt][2] - mn1);
            float p3 = __expf(sacc[nt][3] - mn1);
            sacc[nt][0] = p0; sacc[nt][1] = p1;
            sacc[nt][2] = p2; sacc[nt][3] = p3;
            rs0 += p0 + p1;
            rs1 += p2 + p3;
        }
        rs0 += __shfl_xor_sync(0xffffffffu, rs0, 1);
        rs0 += __shfl_xor_sync(0xffffffffu, rs0, 2);
        rs1 += __shfl_xor_sync(0xffffffffu, rs1, 1);
        rs1 += __shfl_xor_sync(0xffffffffu, rs1, 2);
        l0 = l0 * c0 + rs0;  m0 = mn0;
        l1 = l1 * c1 + rs1;  m1 = mn1;
#pragma unroll
        for (int nt = 0; nt < 8; nt++) {
            oacc[nt][0] *= c0; oacc[nt][1] *= c0;
            oacc[nt][2] *= c1; oacc[nt][3] *= c1;
        }

#pragma unroll
        for (int kt = 0; kt < 8; kt++) {
            uint32_t ahi[4], alo[4];
            splitbf(sacc[2*kt][0],     sacc[2*kt][1],     ahi[0], alo[0]);
            splitbf(sacc[2*kt][2],     sacc[2*kt][3],     ahi[1], alo[1]);
            splitbf(sacc[2*kt + 1][0], sacc[2*kt + 1][1], ahi[2], alo[2]);
            splitbf(sacc[2*kt + 1][2], sacc[2*kt + 1][3], ahi[3], alo[3]);
#pragma unroll
            for (int nt = 0; nt < 8; nt++) {
                uint32_t bh0, bh1, bl0, bl1;
                ldsm_x4(bh0, bh1, bl0, bl1,
                        stV + nt * (8 * KR_V * 4) + kt * 32);
                uint32_t bh[2] = {bh0, bh1}, bl[2] = {bl0, bl1};
                mma_bf16(oacc[nt], ahi, bh, oacc[nt]);
                mma_bf16(oacc[nt], alo, bh, oacc[nt]);
                mma_bf16(oacc[nt], ahi, bl, oacc[nt]);
            }
        }
    }

    float inv0 = 1.0f / l0, inv1 = 1.0f / l1;
#pragma unroll
    for (int nt = 0; nt < 8; nt++) {
        int col = h * HD + nt * 8 + tg2;
        float2 w0, w1;
        w0.x = roundtf(oacc[nt][0] * inv0); w0.y = roundtf(oacc[nt][1] * inv0);
        w1.x = roundtf(oacc[nt][2] * inv1); w1.y = roundtf(oacc[nt][3] * inv1);
        *(float2*)&op[(size_t)(qb * 128 + fr) * D_MODEL + col]     = w0;
        *(float2*)&op[(size_t)(qb * 128 + fr + 8) * D_MODEL + col] = w1;
    }
}

// ---------------- launch ---------------------------------------------------
extern "C" void kernel_launch(void* const* d_in, const int* in_sizes, int n_in,
                              void* d_out, int out_size)
{
    const float* X  = (const float*)d_in[0];
    const float* Wq = (const float*)d_in[1];
    const float* Wk = (const float*)d_in[2];
    const float* Wv = (const float*)d_in[3];
    const float* W1 = (const float*)d_in[4];
    const float* W2 = (const float*)d_in[5];
    float* out = (float*)d_out;

    float *gq, *gk, *gv, *ga, *gh;
    float *gxt, *gwqt, *gwkt, *gwvt, *gw1t, *gw2t;
    uint32_t *gkh, *gkl, *gvh, *gvl;
    cudaGetSymbolAddress((void**)&gq, g_q);
    cudaGetSymbolAddress((void**)&gk, g_k);
    cudaGetSymbolAddress((void**)&gv, g_v);
    cudaGetSymbolAddress((void**)&ga, g_attn);
    cudaGetSymbolAddress((void**)&gh, g_h1);
    cudaGetSymbolAddress((void**)&gxt, g_xt);
    cudaGetSymbolAddress((void**)&gwqt, g_wqt);
    cudaGetSymbolAddress((void**)&gwkt, g_wkt);
    cudaGetSymbolAddress((void**)&gwvt, g_wvt);
    cudaGetSymbolAddress((void**)&gw1t, g_w1t);
    cudaGetSymbolAddress((void**)&gw2t, g_w2t);
    cudaGetSymbolAddress((void**)&gkh, g_khp);
    cudaGetSymbolAddress((void**)&gkl, g_klp);
    cudaGetSymbolAddress((void**)&gvh, g_vhp);
    cudaGetSymbolAddress((void**)&gvl, g_vlp);

    cudaFuncSetAttribute(attn_bf16_kernel,
                         cudaFuncAttributeMaxDynamicSharedMemorySize, ATT_SMEM);
    cudaFuncSetAttribute(qkv_kernel,
                         cudaFuncAttributeMaxDynamicSharedMemorySize, GEMM_SMEM);
    cudaFuncSetAttribute(tgemm2_kernel<1, 1>,
                         cudaFuncAttributeMaxDynamicSharedMemorySize, GEMM_SMEM);
    cudaFuncSetAttribute(tgemm2_kernel<0, 0>,
                         cudaFuncAttributeMaxDynamicSharedMemorySize, GEMM_SMEM);

    // merged pre-round + rope table
    round_all_kernel<<<3968, 256>>>(X, Wq, Wk, Wv, W1, W2);
    qkv_kernel<<<dim3(12, T_SEQ / 128), 256, GEMM_SMEM>>>(
        gxt, gwqt, gwkt, gwvt, gq, gk, gv);
    prep_kv_kernel<<<4096, 256>>>();
    attn_bf16_kernel<<<dim3(T_SEQ / 128, NH), 256, ATT_SMEM>>>(
        gq, gkh, gkl, gvh, gvl, ga);
    tgemm2_kernel<1, 1><<<dim3(D_FF / 128, T_SEQ / 128), 256, GEMM_SMEM>>>(
        ga, gw1t, gh, D_FF, D_MODEL);
    tgemm2_kernel<0, 0><<<dim3(D_MODEL / 128, T_SEQ / 128), 256, GEMM_SMEM>>>(
        gh, gw2t, out, D_MODEL, D_FF);
}

// round 17
// speedup vs baseline: 1.3622x; 1.0005x over previous
#include <cuda_runtime.h>
#include <cuda_bf16.h>
#include <math.h>
#include <stdint.h>

// Problem constants
#define T_SEQ  4096
#define D_MODEL 1024
#define NH     16
#define NKV    4
#define HD     64
#define D_FF   4096

// ---------------- scratch (device globals; no allocation allowed) ----------
__device__ float g_q[T_SEQ * D_MODEL];          // raw (pre-rope) Q
__device__ float g_k[T_SEQ * NKV * HD];         // [token][256] (pre-rope)
__device__ float g_v[NKV * HD * T_SEQ];         // TRANSPOSED [256][4096]
__device__ float g_attn[T_SEQ * D_MODEL];       // tf32-rounded
__device__ float g_h1[(size_t)T_SEQ * D_FF];    // tf32-rounded
__device__ float g_cos[T_SEQ * 32];
__device__ float g_sin[T_SEQ * 32];
__device__ float g_xt[T_SEQ * D_MODEL];
__device__ float g_wqt[D_MODEL * D_MODEL];
__device__ float g_wkt[D_MODEL * NKV * HD];
__device__ float g_wvt[D_MODEL * NKV * HD];
__device__ float g_w1t[D_MODEL * D_FF];
__device__ float g_w2t[D_FF * D_MODEL];
__device__ uint32_t g_khp[T_SEQ * 128];         // [token][kvh*32 + d2] bf16x2 hi
__device__ uint32_t g_klp[T_SEQ * 128];
__device__ uint32_t g_vhp[NKV * HD * (T_SEQ / 2)];  // [dim][token-pair]
__device__ uint32_t g_vlp[NKV * HD * (T_SEQ / 2)];

// ---------------- helpers ---------------------------------------------------
__device__ __forceinline__ uint32_t f2tf32(float x) {
    uint32_t r;
    asm("cvt.rna.tf32.f32 %0, %1;" : "=r"(r) : "f"(x));
    return r;
}
__device__ __forceinline__ float roundtf(float x) {
    return __uint_as_float(f2tf32(x));
}

__device__ __forceinline__ void mma_tf32(float* d, const uint32_t* a,
                                         const uint32_t* b, const float* c) {
    asm volatile(
        "mma.sync.aligned.m16n8k8.row.col.f32.tf32.tf32.f32 "
        "{%0,%1,%2,%3}, {%4,%5,%6,%7}, {%8,%9}, {%10,%11,%12,%13};"
        : "=f"(d[0]), "=f"(d[1]), "=f"(d[2]), "=f"(d[3])
        : "r"(a[0]), "r"(a[1]), "r"(a[2]), "r"(a[3]),
          "r"(b[0]), "r"(b[1]),
          "f"(c[0]), "f"(c[1]), "f"(c[2]), "f"(c[3]));
}

__device__ __forceinline__ void mma_bf16(float* d, const uint32_t* a,
                                         const uint32_t* b, const float* c) {
    asm volatile(
        "mma.sync.aligned.m16n8k16.row.col.f32.bf16.bf16.f32 "
        "{%0,%1,%2,%3}, {%4,%5,%6,%7}, {%8,%9}, {%10,%11,%12,%13};"
        : "=f"(d[0]), "=f"(d[1]), "=f"(d[2]), "=f"(d[3])
        : "r"(a[0]), "r"(a[1]), "r"(a[2]), "r"(a[3]),
          "r"(b[0]), "r"(b[1]),
          "f"(c[0]), "f"(c[1]), "f"(c[2]), "f"(c[3]));
}

__device__ __forceinline__ void ldsm_x4(uint32_t& r0, uint32_t& r1,
                                        uint32_t& r2, uint32_t& r3,
                                        uint32_t saddr) {
    asm volatile(
        "ldmatrix.sync.aligned.m8n8.x4.shared.b16 {%0,%1,%2,%3}, [%4];"
        : "=r"(r0), "=r"(r1), "=r"(r2), "=r"(r3) : "r"(saddr));
}

__device__ __forceinline__ uint32_t packbf(float x, float y) {
    __nv_bfloat162 t = __floats2bfloat162_rn(x, y);
    return *(uint32_t*)&t;
}
__device__ __forceinline__ void splitbf(float x, float y,
                                        uint32_t& hi, uint32_t& lo) {
    __nv_bfloat16 hx = __float2bfloat16_rn(x);
    __nv_bfloat16 hy = __float2bfloat16_rn(y);
    hi = packbf(__bfloat162float(hx), __bfloat162float(hy));
    lo = packbf(x - __bfloat162float(hx), y - __bfloat162float(hy));
}

__device__ __forceinline__ void cp16(float* smem_dst, const float* g) {
    uint32_t a = (uint32_t)__cvta_generic_to_shared(smem_dst);
    asm volatile("cp.async.ca.shared.global [%0], [%1], 16;" :: "r"(a), "l"(g));
}
__device__ __forceinline__ void cp16u(uint32_t* smem_dst, const uint32_t* g) {
    uint32_t a = (uint32_t)__cvta_generic_to_shared(smem_dst);
    asm volatile("cp.async.ca.shared.global [%0], [%1], 16;" :: "r"(a), "l"(g));
}

// ---------------- merged pre-round + rope-table pass ------------------------
__global__ void round_all_kernel(
    const float* __restrict__ X,  const float* __restrict__ Wq,
    const float* __restrict__ Wk, const float* __restrict__ Wv,
    const float* __restrict__ W1, const float* __restrict__ W2)
{
    int b = blockIdx.x;
    if (b >= 3456) {
        int idx = (b - 3456) * 256 + threadIdx.x;
        int i = idx & 31;
        float inv = 1.0f / powf(10000.0f, (float)(2 * i) / 64.0f);
        float ang = (float)(idx >> 5) * inv;
        g_cos[idx] = cosf(ang);
        g_sin[idx] = sinf(ang);
        return;
    }
    const float* src;
    float* dst;
    int base;
    if      (b < 1024) { src = X;  dst = g_xt;  base = 0;    }
    else if (b < 1280) { src = Wq; dst = g_wqt; base = 1024; }
    else if (b < 1344) { src = Wk; dst = g_wkt; base = 1280; }
    else if (b < 1408) { src = Wv; dst = g_wvt; base = 1344; }
    else if (b < 2432) { src = W1; dst = g_w1t; base = 1408; }
    else               { src = W2; dst = g_w2t; base = 2432; }
    size_t off = (size_t)(b - base) * 1024 + threadIdx.x;
#pragma unroll
    for (int j = 0; j < 4; j++) {
        float4 v = ((const float4*)src)[off + j * 256];
        v.x = roundtf(v.x); v.y = roundtf(v.y);
        v.z = roundtf(v.z); v.w = roundtf(v.w);
        ((float4*)dst)[off + j * 256] = v;
    }
}

// ---------------- fused KV prep ---------------------------------------------
__global__ void prep_kv_kernel() {
    int b = blockIdx.x;
    if (b < 2048) {
        __shared__ float buf[2][NKV][64];
        int sub = threadIdx.x >> 7;
        int wt  = threadIdx.x & 127;
        int t = b * 2 + sub;
        int h = wt >> 5;
        int i = wt & 31;
        float c = g_cos[t * 32 + i];
        float s = g_sin[t * 32 + i];
        const float* p = g_k + (size_t)t * (NKV * HD) + h * HD;
        float x1 = p[i], x2 = p[i + 32];
        buf[sub][h][i]      = x1 * c - x2 * s;
        buf[sub][h][i + 32] = x2 * c + x1 * s;
        __syncthreads();
        float a = buf[sub][h][2 * i], bb = buf[sub][h][2 * i + 1];
        uint32_t hi, lo;
        splitbf(a, bb, hi, lo);
        g_khp[t * 128 + h * 32 + i] = hi;
        g_klp[t * 128 + h * 32 + i] = lo;
    } else {
        int idx = (b - 2048) * 256 + threadIdx.x;
        float2 v = *(const float2*)&g_v[(size_t)idx * 2];
        uint32_t hi, lo;
        splitbf(v.x, v.y, hi, lo);
        g_vhp[idx] = hi;
        g_vlp[idx] = lo;
    }
}

// ---------------- cp.async tf32 GEMM (R10 proven: BK=16, 4-stage, ldsm A) ---
#define AS_ST 20
#define BS_ST 136
#define AS_STAGE (128 * AS_ST)
#define BS_STAGE (16 * BS_ST)
#define GEMM_SMEM ((4 * (AS_STAGE + BS_STAGE)) * 4)

template <int SILU, int ROUND, int TRANSC>
__device__ __forceinline__ void gemm_body(
    const float* __restrict__ A, const float* __restrict__ B,
    float* __restrict__ C, int N, int K, int rowBase, int colBase)
{
    extern __shared__ float smp[];
    float* As = smp;
    float* Bs = smp + 4 * AS_STAGE;

    int tid  = threadIdx.x;
    int lane = tid & 31;
    int warp = tid >> 5;
    int wm = (warp & 1) * 64;
    int wn = (warp >> 1) * 32;

    int ar  = tid >> 2;
    int ac  = (tid & 3) << 2;
    int bkr = tid >> 5;
    int bc  = (tid & 31) << 2;

    const float* Ag0 = A + (size_t)(rowBase + ar) * K + ac;
    const float* Ag1 = A + (size_t)(rowBase + 64 + ar) * K + ac;
    const float* Bg  = B + colBase + bc;

    uint32_t smem_b = (uint32_t)__cvta_generic_to_shared(smp);
    uint32_t loA = ((wm + (lane & 7) + ((lane >> 3) & 1) * 8) * AS_ST
                    + (lane >> 4) * 4) * 4;

    int nk = K >> 4;

#pragma unroll
    for (int s = 0; s < 3; s++) {
        if (s < nk) {
            float* as = As + s * AS_STAGE;
            float* bs = Bs + s * BS_STAGE;
            int k0 = s << 4;
            cp16(as + ar * AS_ST + ac,        Ag0 + k0);
            cp16(as + (ar + 64) * AS_ST + ac, Ag1 + k0);
            cp16(bs + bkr * BS_ST + bc,       Bg + (size_t)(k0 + bkr) * N);
            cp16(bs + (bkr + 8) * BS_ST + bc, Bg + (size_t)(k0 + 8 + bkr) * N);
        }
        asm volatile("cp.async.commit_group;");
    }

    float acc[4][4][4];
#pragma unroll
    for (int i = 0; i < 4; i++)
#pragma unroll
        for (int j = 0; j < 4; j++)
#pragma unroll
            for (int q = 0; q < 4; q++) acc[i][j][q] = 0.0f;

    for (int kt = 0; kt < nk; kt++) {
        asm volatile("cp.async.wait_group 2;");
        __syncthreads();

        int nx = kt + 3;
        if (nx < nk) {
            int bufn = nx & 3;
            float* as = As + bufn * AS_STAGE;
            float* bs = Bs + bufn * BS_STAGE;
            int k0 = nx << 4;
            cp16(as + ar * AS_ST + ac,        Ag0 + k0);
            cp16(as + (ar + 64) * AS_ST + ac, Ag1 + k0);
            cp16(bs + bkr * BS_ST + bc,       Bg + (size_t)(k0 + bkr) * N);
            cp16(bs + (bkr + 8) * BS_ST + bc, Bg + (size_t)(k0 + 8 + bkr) * N);
        }
        asm volatile("cp.async.commit_group;");

        uint32_t asb = smem_b + ((kt & 3) * AS_STAGE) * 4 + loA;
        const float* bs = Bs + (kt & 3) * BS_STAGE;
#pragma unroll
        for (int ks = 0; ks < 16; ks += 8) {
            uint32_t af[4][4], bf[4][2];
#pragma unroll
            for (int i = 0; i < 4; i++) {
                ldsm_x4(af[i][0], af[i][1], af[i][2], af[i][3],
                        asb + (i * 16 * AS_ST + ks) * 4);
            }
#pragma unroll
            for (int j = 0; j < 4; j++) {
                int kk = ks + (lane & 3);
                int n  = wn + j * 8 + (lane >> 2);
                bf[j][0] = __float_as_uint(bs[kk * BS_ST + n]);
                bf[j][1] = __float_as_uint(bs[(kk + 4) * BS_ST + n]);
            }
#pragma unroll
            for (int i = 0; i < 4; i++)
#pragma unroll
                for (int j = 0; j < 4; j++)
                    mma_tf32(acc[i][j], af[i], bf[j], acc[i][j]);
        }
    }

#pragma unroll
    for (int i = 0; i < 4; i++) {
        int r0 = rowBase + wm + i * 16 + (lane >> 2);
#pragma unroll
        for (int j = 0; j < 4; j++) {
            int c0 = colBase + wn + j * 8 + (lane & 3) * 2;
            float2 v0, v1;
            v0.x = acc[i][j][0]; v0.y = acc[i][j][1];
            v1.x = acc[i][j][2]; v1.y = acc[i][j][3];
            if (SILU) {
                v0.x = v0.x / (1.0f + expf(-v0.x));
                v0.y = v0.y / (1.0f + expf(-v0.y));
                v1.x = v1.x / (1.0f + expf(-v1.x));
                v1.y = v1.y / (1.0f + expf(-v1.y));
            }
            if (ROUND) {
                v0.x = roundtf(v0.x); v0.y = roundtf(v0.y);
                v1.x = roundtf(v1.x); v1.y = roundtf(v1.y);
            }
            if (TRANSC) {
                C[(size_t)c0 * T_SEQ + r0]           = v0.x;
                C[(size_t)(c0 + 1) * T_SEQ + r0]     = v0.y;
                C[(size_t)c0 * T_SEQ + r0 + 8]       = v1.x;
                C[(size_t)(c0 + 1) * T_SEQ + r0 + 8] = v1.y;
            } else {
                *(float2*)&C[(size_t)r0 * N + c0]       = v0;
                *(float2*)&C[(size_t)(r0 + 8) * N + c0] = v1;
            }
        }
    }
}

template <int SILU, int ROUND>
__global__ void __launch_bounds__(256, 2) tgemm2_kernel(
    const float* __restrict__ A, const float* __restrict__ B,
    float* __restrict__ C, int N, int K)
{
    gemm_body<SILU, ROUND, 0>(A, B, C, N, K, blockIdx.y * 128, blockIdx.x * 128);
}

__global__ void __launch_bounds__(256, 2) qkv_kernel(
    const float* __restrict__ Xt,
    const float* __restrict__ Wqt, const float* __restrict__ Wkt,
    const float* __restrict__ Wvt,
    float* __restrict__ q, float* __restrict__ k, float* __restrict__ v)
{
    int bx = blockIdx.x;
    if (bx < 8) {
        gemm_body<0, 0, 0>(Xt, Wqt, q, D_MODEL, D_MODEL,
                           blockIdx.y * 128, bx * 128);
    } else if (bx < 10) {
        gemm_body<0, 0, 0>(Xt, Wkt, k, NKV * HD, D_MODEL,
                           blockIdx.y * 128, (bx - 8) * 128);
    } else {
        gemm_body<0, 0, 1>(Xt, Wvt, v, NKV * HD, D_MODEL,
                           blockIdx.y * 128, (bx - 10) * 128);
    }
}

// ---------------- bf16 MMA flash attention (BM=128, BN=128) ----------------
// RoPE-Q fused; ks-outer S loop; ldsm prefetch one nt ahead in S and PV.
#define KR_K 68
#define KR_V 132
#define KARR (128 * KR_K)           // 8704 u32
#define VARR (64 * KR_V)            // 8448 u32
#define STAGE_U (KARR + VARR)       // 17152 u32
#define ATT_SMEM (2 * STAGE_U * 4)  // 137216 bytes

__global__ void __launch_bounds__(256) attn_bf16_kernel(
    const float* __restrict__ qp,
    const uint32_t* __restrict__ khp, const uint32_t* __restrict__ klp,
    const uint32_t* __restrict__ vhp, const uint32_t* __restrict__ vlp,
    float* __restrict__ op)
{
    extern __shared__ uint32_t smu[];
    float* Qs = (float*)smu;

    int qb   = gridDim.x - 1 - blockIdx.x;
    int h    = blockIdx.y;
    int kvh  = h >> 2;
    int tid  = threadIdx.x;
    int lane = tid & 31;
    int warp = tid >> 5;
    int gid  = lane >> 2;
    int tig  = lane & 3;
    int tg2  = tig * 2;
    int fr   = warp * 16 + gid;

    // ---- stage raw Q tile ----
#pragma unroll
    for (int i = 0; i < 8; i++) {
        int e = tid + 256 * i;
        int r = e >> 4, c4 = (e & 15) << 2;
        *(float4*)&Qs[r * 64 + c4] =
            *(const float4*)&qp[(size_t)(qb * 128 + r) * D_MODEL + h * HD + c4];
    }
    __syncthreads();

    // ---- in-place RoPE ----
#pragma unroll
    for (int it = 0; it < 16; it++) {
        int p = tid + 256 * it;
        int r = p >> 5, i = p & 31;
        float c = g_cos[(qb * 128 + r) * 32 + i];
        float s = g_sin[(qb * 128 + r) * 32 + i];
        float x1 = Qs[r * 64 + i], x2 = Qs[r * 64 + i + 32];
        Qs[r * 64 + i]      = x1 * c - x2 * s;
        Qs[r * 64 + i + 32] = x2 * c + x1 * s;
    }
    __syncthreads();

    uint32_t qhi[4][4], qlo[4][4];
#pragma unroll
    for (int kt = 0; kt < 4; kt++) {
        float2 x0 = *(float2*)&Qs[fr * 64 + kt * 16 + tg2];
        float2 x1 = *(float2*)&Qs[(fr + 8) * 64 + kt * 16 + tg2];
        float2 x2 = *(float2*)&Qs[fr * 64 + kt * 16 + tg2 + 8];
        float2 x3 = *(float2*)&Qs[(fr + 8) * 64 + kt * 16 + tg2 + 8];
        splitbf(x0.x * 0.125f, x0.y * 0.125f, qhi[kt][0], qlo[kt][0]);
        splitbf(x1.x * 0.125f, x1.y * 0.125f, qhi[kt][1], qlo[kt][1]);
        splitbf(x2.x * 0.125f, x2.y * 0.125f, qhi[kt][2], qlo[kt][2]);
        splitbf(x3.x * 0.125f, x3.y * 0.125f, qhi[kt][3], qlo[kt][3]);
    }
    __syncthreads();   // Q reads done before cp.async overwrites stage 0

    uint32_t smem_b = (uint32_t)__cvta_generic_to_shared(smu);
    int loK = (lane & 7) * KR_K + ((lane >> 3) & 1) * 4 + (lane >> 4) * 32;
    int loV = (lane & 7) * KR_V + ((lane >> 3) & 1) * 4 + (lane >> 4) * 64;

    int rK = tid >> 1, hK = (tid & 1) * 16;
    int rV = tid >> 2, qV = (tid & 3) * 16;
    const uint32_t* khB = khp + kvh * 32;
    const uint32_t* klB = klp + kvh * 32;
    const uint32_t* vhB = vhp + (size_t)(kvh * HD + rV) * (T_SEQ / 2);
    const uint32_t* vlB = vlp + (size_t)(kvh * HD + rV) * (T_SEQ / 2);

    int kbmax = qb;

    {
        uint32_t* Ks = smu;
        uint32_t* Vs = smu + KARR;
#pragma unroll
        for (int j = 0; j < 4; j++) {
            int c = hK + j * 4;
            cp16u(Ks + rK * KR_K + c,      khB + (size_t)rK * 128 + c);
            cp16u(Ks + rK * KR_K + 32 + c, klB + (size_t)rK * 128 + c);
        }
#pragma unroll
        for (int j = 0; j < 4; j++) {
            int c = qV + j * 4;
            cp16u(Vs + rV * KR_V + c,      vhB + c);
            cp16u(Vs + rV * KR_V + 64 + c, vlB + c);
        }
        asm volatile("cp.async.commit_group;");
    }

    float oacc[8][4];
#pragma unroll
    for (int nt = 0; nt < 8; nt++)
#pragma unroll
        for (int j = 0; j < 4; j++) oacc[nt][j] = 0.0f;
    float m0 = -1e30f, m1 = -1e30f, l0 = 0.0f, l1 = 0.0f;

    for (int kb = 0; kb <= kbmax; kb++) {
        asm volatile("cp.async.wait_group 0;");
        __syncthreads();

        if (kb < kbmax) {
            uint32_t* st = smu + ((kb + 1) & 1) * STAGE_U;
            uint32_t* Ks = st;
            uint32_t* Vs = st + KARR;
            int tk = (kb + 1) * 128;
            int tv = (kb + 1) * 64;
#pragma unroll
            for (int j = 0; j < 4; j++) {
                int c = hK + j * 4;
                cp16u(Ks + rK * KR_K + c,      khB + (size_t)(tk + rK) * 128 + c);
                cp16u(Ks + rK * KR_K + 32 + c, klB + (size_t)(tk + rK) * 128 + c);
            }
#pragma unroll
            for (int j = 0; j < 4; j++) {
                int c = qV + j * 4;
                cp16u(Vs + rV * KR_V + c,      vhB + tv + c);
                cp16u(Vs + rV * KR_V + 64 + c, vlB + tv + c);
            }
        }
        asm volatile("cp.async.commit_group;");

        uint32_t stK = smem_b + 4 * ((kb & 1) * STAGE_U + loK);
        uint32_t stV = smem_b + 4 * ((kb & 1) * STAGE_U + KARR + loV);

        // ---- S = (Q/8) @ K^T : ks outer, nt inner, ldsm prefetch +1 ----
        float sacc[16][4];
#pragma unroll
        for (int nt = 0; nt < 16; nt++)
#pragma unroll
            for (int j = 0; j < 4; j++) sacc[nt][j] = 0.0f;

#pragma unroll
        for (int ks = 0; ks < 4; ks++) {
            uint32_t pf0, pf1, pf2, pf3;
            ldsm_x4(pf0, pf1, pf2, pf3, stK + ks * 32);
#pragma unroll
            for (int nt = 0; nt < 16; nt++) {
                uint32_t bh[2] = {pf0, pf1}, bl[2] = {pf2, pf3};
                if (nt < 15)
                    ldsm_x4(pf0, pf1, pf2, pf3,
                            stK + (nt + 1) * (8 * KR_K * 4) + ks * 32);
                mma_bf16(sacc[nt], qhi[ks], bh, sacc[nt]);
                mma_bf16(sacc[nt], qlo[ks], bh, sacc[nt]);
                mma_bf16(sacc[nt], qhi[ks], bl, sacc[nt]);
            }
        }

        if (kb == qb) {
            int grow0 = qb * 128 + fr;
            int grow1 = grow0 + 8;
#pragma unroll
            for (int nt = 0; nt < 16; nt++) {
                int gc = kb * 128 + nt * 8 + tg2;
                if (gc     > grow0) sacc[nt][0] = -1e30f;
                if (gc + 1 > grow0) sacc[nt][1] = -1e30f;
                if (gc     > grow1) sacc[nt][2] = -1e30f;
                if (gc + 1 > grow1) sacc[nt][3] = -1e30f;
            }
        }

        float mx0 = -1e30f, mx1 = -1e30f;
#pragma unroll
        for (int nt = 0; nt < 16; nt++) {
            mx0 = fmaxf(mx0, fmaxf(sacc[nt][0], sacc[nt][1]));
            mx1 = fmaxf(mx1, fmaxf(sacc[nt][2], sacc[nt][3]));
        }
        mx0 = fmaxf(mx0, __shfl_xor_sync(0xffffffffu, mx0, 1));
        mx0 = fmaxf(mx0, __shfl_xor_sync(0xffffffffu, mx0, 2));
        mx1 = fmaxf(mx1, __shfl_xor_sync(0xffffffffu, mx1, 1));
        mx1 = fmaxf(mx1, __shfl_xor_sync(0xffffffffu, mx1, 2));

        float mn0 = fmaxf(m0, mx0), mn1 = fmaxf(m1, mx1);
        float c0 = __expf(m0 - mn0), c1 = __expf(m1 - mn1);
        float rs0 = 0.0f, rs1 = 0.0f;
#pragma unroll
        for (int nt = 0; nt < 16; nt++) {
            float p0 = __expf(sacc[nt][0] - mn0);
            float p1 = __expf(sacc[nt][1] - mn0);
            float p2 = __expf(sacc[nt][2] - mn1);
            float p3 = __expf(sacc[nt][3] - mn1);
            sacc[nt][0] = p0; sacc[nt][1] = p1;
            sacc[nt][2] = p2; sacc[nt][3] = p3;
            rs0 += p0 + p1;
            rs1 += p2 + p3;
        }
        rs0 += __shfl_xor_sync(0xffffffffu, rs0, 1);
        rs0 += __shfl_xor_sync(0xffffffffu, rs0, 2);
        rs1 += __shfl_xor_sync(0xffffffffu, rs1, 1);
        rs1 += __shfl_xor_sync(0xffffffffu, rs1, 2);
        l0 = l0 * c0 + rs0;  m0 = mn0;
        l1 = l1 * c1 + rs1;  m1 = mn1;
#pragma unroll
        for (int nt = 0; nt < 8; nt++) {
            oacc[nt][0] *= c0; oacc[nt][1] *= c0;
            oacc[nt][2] *= c1; oacc[nt][3] *= c1;
        }

        // ---- O += P @ V : A from sacc regs, V ldsm prefetch +1 ----
#pragma unroll
        for (int kt = 0; kt < 8; kt++) {
            uint32_t ahi[4], alo[4];
            splitbf(sacc[2*kt][0],     sacc[2*kt][1],     ahi[0], alo[0]);
            splitbf(sacc[2*kt][2],     sacc[2*kt][3],     ahi[1], alo[1]);
            splitbf(sacc[2*kt + 1][0], sacc[2*kt + 1][1], ahi[2], alo[2]);
            splitbf(sacc[2*kt + 1][2], sacc[2*kt + 1][3], ahi[3], alo[3]);
            uint32_t pf0, pf1, pf2, pf3;
            ldsm_x4(pf0, pf1, pf2, pf3, stV + kt * 32);
#pragma unroll
            for (int nt = 0; nt < 8; nt++) {
                uint32_t bh[2] = {pf0, pf1}, bl[2] = {pf2, pf3};
                if (nt < 7)
                    ldsm_x4(pf0, pf1, pf2, pf3,
                            stV + (nt + 1) * (8 * KR_V * 4) + kt * 32);
                mma_bf16(oacc[nt], ahi, bh, oacc[nt]);
                mma_bf16(oacc[nt], alo, bh, oacc[nt]);
                mma_bf16(oacc[nt], ahi, bl, oacc[nt]);
            }
        }
    }

    float inv0 = 1.0f / l0, inv1 = 1.0f / l1;
#pragma unroll
    for (int nt = 0; nt < 8; nt++) {
        int col = h * HD + nt * 8 + tg2;
        float2 w0, w1;
        w0.x = roundtf(oacc[nt][0] * inv0); w0.y = roundtf(oacc[nt][1] * inv0);
        w1.x = roundtf(oacc[nt][2] * inv1); w1.y = roundtf(oacc[nt][3] * inv1);
        *(float2*)&op[(size_t)(qb * 128 + fr) * D_MODEL + col]     = w0;
        *(float2*)&op[(size_t)(qb * 128 + fr + 8) * D_MODEL + col] = w1;
    }
}

// ---------------- launch ---------------------------------------------------
extern "C" void kernel_launch(void* const* d_in, const int* in_sizes, int n_in,
                              void* d_out, int out_size)
{
    const float* X  = (const float*)d_in[0];
    const float* Wq = (const float*)d_in[1];
    const float* Wk = (const float*)d_in[2];
    const float* Wv = (const float*)d_in[3];
    const float* W1 = (const float*)d_in[4];
    const float* W2 = (const float*)d_in[5];
    float* out = (float*)d_out;

    float *gq, *gk, *gv, *ga, *gh;
    float *gxt, *gwqt, *gwkt, *gwvt, *gw1t, *gw2t;
    uint32_t *gkh, *gkl, *gvh, *gvl;
    cudaGetSymbolAddress((void**)&gq, g_q);
    cudaGetSymbolAddress((void**)&gk, g_k);
    cudaGetSymbolAddress((void**)&gv, g_v);
    cudaGetSymbolAddress((void**)&ga, g_attn);
    cudaGetSymbolAddress((void**)&gh, g_h1);
    cudaGetSymbolAddress((void**)&gxt, g_xt);
    cudaGetSymbolAddress((void**)&gwqt, g_wqt);
    cudaGetSymbolAddress((void**)&gwkt, g_wkt);
    cudaGetSymbolAddress((void**)&gwvt, g_wvt);
    cudaGetSymbolAddress((void**)&gw1t, g_w1t);
    cudaGetSymbolAddress((void**)&gw2t, g_w2t);
    cudaGetSymbolAddress((void**)&gkh, g_khp);
    cudaGetSymbolAddress((void**)&gkl, g_klp);
    cudaGetSymbolAddress((void**)&gvh, g_vhp);
    cudaGetSymbolAddress((void**)&gvl, g_vlp);

    cudaFuncSetAttribute(attn_bf16_kernel,
                         cudaFuncAttributeMaxDynamicSharedMemorySize, ATT_SMEM);
    cudaFuncSetAttribute(qkv_kernel,
                         cudaFuncAttributeMaxDynamicSharedMemorySize, GEMM_SMEM);
    cudaFuncSetAttribute(tgemm2_kernel<1, 1>,
                         cudaFuncAttributeMaxDynamicSharedMemorySize, GEMM_SMEM);
    cudaFuncSetAttribute(tgemm2_kernel<0, 0>,
                         cudaFuncAttributeMaxDynamicSharedMemorySize, GEMM_SMEM);

    round_all_kernel<<<3968, 256>>>(X, Wq, Wk, Wv, W1, W2);
    qkv_kernel<<<dim3(12, T_SEQ / 128), 256, GEMM_SMEM>>>(
        gxt, gwqt, gwkt, gwvt, gq, gk, gv);
    prep_kv_kernel<<<4096, 256>>>();
    attn_bf16_kernel<<<dim3(T_SEQ / 128, NH), 256, ATT_SMEM>>>(
        gq, gkh, gkl, gvh, gvl, ga);
    tgemm2_kernel<1, 1><<<dim3(D_FF / 128, T_SEQ / 128), 256, GEMM_SMEM>>>(
        ga, gw1t, gh, D_FF, D_MODEL);
    tgemm2_kernel<0, 0><<<dim3(D_MODEL / 128, T_SEQ / 128), 256, GEMM_SMEM>>>(
        gh, gw2t, out, D_MODEL, D_FF);
}